// round 13
// baseline (speedup 1.0000x reference)
#include <cuda_runtime.h>
#include <cuda_bf16.h>
#include <cuda_fp16.h>
#include <cstdint>

#define Nn   100000
#define Ee   1600000
#define F1   128                // HEADS*HID
#define OUTF 64
#define NEG_SLOPE 0.2f
#define NB   ((Nn + 1023) / 1024)   // scan blocks
#define HALF 50048                  // 391 * 128, pipeline split point

// ---------------- scratch (static device globals; no allocation) ------------
__device__ __align__(16) __half g_h1h[Nn * F1];     // layer1 features (fp16)
__device__ __align__(16) float  g_agg1[Nn * F1];    // layer1 out (fp32, GEMM2 input)
__device__ __align__(16) __half g_h2h[Nn * OUTF];   // layer2 features (fp16)
__device__ float4 g_es1[Nn], g_ed1[Nn];
__device__ float  g_es2[Nn], g_ed2[Nn];
__device__ int    g_src[Ee], g_dst[Ee];
__device__ int    g_cnt[Nn];
__device__ int    g_rowptr[Nn];
__device__ int    g_woff[Nn];
__device__ int    g_bsum[NB], g_boff[NB];
__device__ int    g_csrc[Ee];
__device__ int    g_is64;
__device__ __align__(16) __nv_bfloat16 g_Wt1_hi[128 * 128], g_Wt1_lo[128 * 128];
__device__ __align__(16) __nv_bfloat16 g_Wt2_hi[64 * 128],  g_Wt2_lo[64 * 128];

// ---------------- helpers ---------------------------------------------------
__device__ __forceinline__ float lrelu(float x) { return x > 0.f ? x : NEG_SLOPE * x; }

__device__ __forceinline__ void mma_bf16(float c[4], uint32_t a0, uint32_t a1,
                                         uint32_t a2, uint32_t a3,
                                         uint32_t b0, uint32_t b1) {
    asm volatile("mma.sync.aligned.m16n8k16.row.col.f32.bf16.bf16.f32 "
                 "{%0,%1,%2,%3}, {%4,%5,%6,%7}, {%8,%9}, {%0,%1,%2,%3};"
                 : "+f"(c[0]), "+f"(c[1]), "+f"(c[2]), "+f"(c[3])
                 : "r"(a0), "r"(a1), "r"(a2), "r"(a3), "r"(b0), "r"(b1));
}

__device__ __forceinline__ void ldsm4(uint32_t r[4], uint32_t addr) {
    asm volatile("ldmatrix.sync.aligned.m8n8.x4.shared.b16 {%0,%1,%2,%3}, [%4];"
                 : "=r"(r[0]), "=r"(r[1]), "=r"(r[2]), "=r"(r[3]) : "r"(addr));
}

// ---------------- dtype detection (parallel) ---------------------------------
__global__ void k_detect(const unsigned int* __restrict__ w) {
    __shared__ int bad;
    if (threadIdx.x == 0) bad = 0;
    __syncthreads();
    for (int j = threadIdx.x; j < 1024; j += 256)
        if (w[1 + 2 * j] != 0u) bad = 1;
    __syncthreads();
    if (threadIdx.x == 0) g_is64 = !bad;
}

__global__ void k_convert_hist(const int* __restrict__ ei) {
    int i = blockIdx.x * blockDim.x + threadIdx.x;
    if (i >= Ee) return;
    int s, d;
    if (g_is64) { s = ei[2 * i]; d = ei[2 * (Ee + i)]; }
    else        { s = ei[i];     d = ei[Ee + i]; }
    s = min(max(s, 0), Nn - 1);
    d = min(max(d, 0), Nn - 1);
    g_src[i] = s;
    g_dst[i] = d;
    atomicAdd(&g_cnt[d], 1);
}

// ---------------- CSR build --------------------------------------------------
__global__ void k_scan_block() {
    __shared__ int sh[1024];
    int t = threadIdx.x;
    int idx = blockIdx.x * 1024 + t;
    int v = (idx < Nn) ? g_cnt[idx] : 0;
    sh[t] = v;
    __syncthreads();
    for (int o = 1; o < 1024; o <<= 1) {
        int add = (t >= o) ? sh[t - o] : 0;
        __syncthreads();
        sh[t] += add;
        __syncthreads();
    }
    if (idx < Nn) g_rowptr[idx] = sh[t] - v;
    if (t == 1023) g_bsum[blockIdx.x] = sh[1023];
}

__global__ void k_scan_top() {          // 1 block x 128 threads, NB <= 128
    int t = threadIdx.x;
    int lane = t & 31, w = t >> 5;
    int v = (t < NB) ? g_bsum[t] : 0;
    int x = v;
#pragma unroll
    for (int o = 1; o < 32; o <<= 1) {
        int y = __shfl_up_sync(0xffffffff, x, o);
        if (lane >= o) x += y;
    }
    __shared__ int ws[4];
    if (lane == 31) ws[w] = x;
    __syncthreads();
    int add = 0;
    for (int i = 0; i < w; i++) add += ws[i];
    if (t < NB) g_boff[t] = x + add - v;   // exclusive
}

__global__ void k_scan_add() {
    int i = blockIdx.x * blockDim.x + threadIdx.x;
    if (i >= Nn) return;
    int r = g_rowptr[i] + g_boff[i >> 10];
    g_rowptr[i] = r;
    g_woff[i] = r;
}

__global__ void k_fill() {
    int i = blockIdx.x * blockDim.x + threadIdx.x;
    if (i >= Ee) return;
    int d = g_dst[i];
    int pos = atomicAdd(&g_woff[d], 1);
    g_csrc[pos] = g_src[i];
}

// ---------------- weight preconversion (transposed bf16 hi/lo) ---------------
__global__ void k_prepW1(const float* __restrict__ W1) {
    int i = blockIdx.x * blockDim.x + threadIdx.x;
    if (i < 128 * 128) {
        int k = i >> 7, n = i & 127;
        float v = W1[i];
        __nv_bfloat16 hi = __float2bfloat16(v);
        g_Wt1_hi[n * 128 + k] = hi;
        g_Wt1_lo[n * 128 + k] = __float2bfloat16(v - __bfloat162float(hi));
    }
}

__global__ void k_prepW2(const float* __restrict__ W2) {
    int i = blockIdx.x * blockDim.x + threadIdx.x;
    if (i < 128 * 64) {
        int k = i / 64, n = i % 64;
        float v = W2[i];
        __nv_bfloat16 hi = __float2bfloat16(v);
        g_Wt2_hi[n * 128 + k] = hi;
        g_Wt2_lo[n * 128 + k] = __float2bfloat16(v - __bfloat162float(hi));
    }
}

// ---------------- bf16 split-K TC GEMM (ldmatrix) with fused scores ----------
template<int BN, int NH>
__global__ void __launch_bounds__(256, 2)
gemm_tc(const float* __restrict__ A,
        const __nv_bfloat16* __restrict__ Bt_hi,
        const __nv_bfloat16* __restrict__ Bt_lo,
        __half* __restrict__ C, int M, int row_start,
        const float* __restrict__ a_src, const float* __restrict__ a_dst,
        float* __restrict__ es_out, float* __restrict__ ed_out) {
    constexpr int K  = 128;
    constexpr int BK = 32;
    constexpr int AP = 40;
    constexpr int NBW = BN / 16;

    __shared__ __nv_bfloat16 As_hi[128 * AP], As_lo[128 * AP];
    __shared__ __nv_bfloat16 Bs_hi[BN * AP],  Bs_lo[BN * AP];
    __shared__ float sm_es[128], sm_ed[128];

    const int tid  = threadIdx.x;
    const int w    = tid >> 5;
    const int lane = tid & 31;
    const int g    = lane >> 2;
    const int q    = lane & 3;
    const int wrow = (w >> 1) * 32;
    const int n0w  = (w & 1) * (BN / 2);
    const int row0 = row_start + blockIdx.x * 128;

    const int a_r = lane & 15;
    const int a_k = (lane >> 4) * 8;
    const int b_r = (lane & 7) + ((lane >> 4) * 8);
    const int b_k = ((lane >> 3) & 1) * 8;

    const uint32_t sAhi = (uint32_t)__cvta_generic_to_shared(As_hi);
    const uint32_t sAlo = (uint32_t)__cvta_generic_to_shared(As_lo);
    const uint32_t sBhi = (uint32_t)__cvta_generic_to_shared(Bs_hi);
    const uint32_t sBlo = (uint32_t)__cvta_generic_to_shared(Bs_lo);

    float c[2][NBW][4];
#pragma unroll
    for (int m = 0; m < 2; m++)
#pragma unroll
        for (int nb = 0; nb < NBW; nb++)
#pragma unroll
            for (int j = 0; j < 4; j++) c[m][nb][j] = 0.f;

    for (int kt = 0; kt < K; kt += BK) {
        __syncthreads();
#pragma unroll
        for (int it = 0; it < 4; it++) {
            int i = tid + it * 256;
            int row = i >> 3, kq = i & 7;
            int gr = row0 + row;
            float4 v = make_float4(0.f, 0.f, 0.f, 0.f);
            if (gr < M) v = *(const float4*)(A + (size_t)gr * K + kt + kq * 4);
            int base = row * AP + kq * 4;
            __nv_bfloat16 h0 = __float2bfloat16(v.x), h1b = __float2bfloat16(v.y);
            __nv_bfloat16 h2 = __float2bfloat16(v.z), h3 = __float2bfloat16(v.w);
            *(__nv_bfloat162*)&As_hi[base]     = __nv_bfloat162(h0, h1b);
            *(__nv_bfloat162*)&As_hi[base + 2] = __nv_bfloat162(h2, h3);
            *(__nv_bfloat162*)&As_lo[base] = __nv_bfloat162(
                __float2bfloat16(v.x - __bfloat162float(h0)),
                __float2bfloat16(v.y - __bfloat162float(h1b)));
            *(__nv_bfloat162*)&As_lo[base + 2] = __nv_bfloat162(
                __float2bfloat16(v.z - __bfloat162float(h2)),
                __float2bfloat16(v.w - __bfloat162float(h3)));
        }
#pragma unroll
        for (int it = 0; it < BN * 4 / 256; it++) {
            int i = tid + it * 256;
            int n = i >> 2, j = i & 3;
            *(uint4*)&Bs_hi[n * AP + j * 8] =
                *(const uint4*)&Bt_hi[n * 128 + kt + j * 8];
            *(uint4*)&Bs_lo[n * AP + j * 8] =
                *(const uint4*)&Bt_lo[n * 128 + kt + j * 8];
        }
        __syncthreads();

#pragma unroll
        for (int kk = 0; kk < BK; kk += 16) {
            uint32_t ahi[2][4], alo[2][4];
#pragma unroll
            for (int m = 0; m < 2; m++) {
                uint32_t off = ((wrow + m * 16 + a_r) * AP + kk + a_k) * 2;
                ldsm4(ahi[m], sAhi + off);
                ldsm4(alo[m], sAlo + off);
            }
#pragma unroll
            for (int nbp = 0; nbp < NBW / 2; nbp++) {
                int nb = 2 * nbp;
                uint32_t off = ((n0w + nb * 8 + b_r) * AP + kk + b_k) * 2;
                uint32_t bh[4], bl[4];
                ldsm4(bh, sBhi + off);
                ldsm4(bl, sBlo + off);
#pragma unroll
                for (int m = 0; m < 2; m++) {
                    mma_bf16(c[m][nb],     ahi[m][0], ahi[m][1], ahi[m][2], ahi[m][3], bh[0], bh[1]);
                    mma_bf16(c[m][nb],     ahi[m][0], ahi[m][1], ahi[m][2], ahi[m][3], bl[0], bl[1]);
                    mma_bf16(c[m][nb],     alo[m][0], alo[m][1], alo[m][2], alo[m][3], bh[0], bh[1]);
                    mma_bf16(c[m][nb + 1], ahi[m][0], ahi[m][1], ahi[m][2], ahi[m][3], bh[2], bh[3]);
                    mma_bf16(c[m][nb + 1], ahi[m][0], ahi[m][1], ahi[m][2], ahi[m][3], bl[2], bl[3]);
                    mma_bf16(c[m][nb + 1], alo[m][0], alo[m][1], alo[m][2], alo[m][3], bh[2], bh[3]);
                }
            }
        }
    }

    // ---- C store (fp16) ----
#pragma unroll
    for (int m = 0; m < 2; m++) {
#pragma unroll
        for (int nb = 0; nb < NBW; nb++) {
            int row = row0 + wrow + m * 16 + g;
            int col = n0w + nb * 8 + 2 * q;
            if (row < M)
                *(__half2*)(C + (size_t)row * BN + col) =
                    __floats2half2_rn(c[m][nb][0], c[m][nb][1]);
            if (row + 8 < M)
                *(__half2*)(C + (size_t)(row + 8) * BN + col) =
                    __floats2half2_rn(c[m][nb][2], c[m][nb][3]);
        }
    }

    // ---- fused score epilogue (fp32 fragments) ----
    constexpr int HW = (NH == 4) ? 2 : 1;
    float pes[4][HW], ped[4][HW];
#pragma unroll
    for (int r = 0; r < 4; r++)
#pragma unroll
        for (int hh = 0; hh < HW; hh++) { pes[r][hh] = 0.f; ped[r][hh] = 0.f; }
#pragma unroll
    for (int nb = 0; nb < NBW; nb++) {
        int colg = n0w + nb * 8 + 2 * q;
        float a0s = a_src[colg], a1s = a_src[colg + 1];
        float a0d = a_dst[colg], a1d = a_dst[colg + 1];
        int hh = (NH == 4) ? (nb / (NBW / 2)) : 0;
#pragma unroll
        for (int m = 0; m < 2; m++) {
            pes[m * 2 + 0][hh] += c[m][nb][0] * a0s + c[m][nb][1] * a1s;
            pes[m * 2 + 1][hh] += c[m][nb][2] * a0s + c[m][nb][3] * a1s;
            ped[m * 2 + 0][hh] += c[m][nb][0] * a0d + c[m][nb][1] * a1d;
            ped[m * 2 + 1][hh] += c[m][nb][2] * a0d + c[m][nb][3] * a1d;
        }
    }
#pragma unroll
    for (int r = 0; r < 4; r++)
#pragma unroll
        for (int hh = 0; hh < HW; hh++) {
            pes[r][hh] += __shfl_xor_sync(0xffffffff, pes[r][hh], 1);
            pes[r][hh] += __shfl_xor_sync(0xffffffff, pes[r][hh], 2);
            ped[r][hh] += __shfl_xor_sync(0xffffffff, ped[r][hh], 1);
            ped[r][hh] += __shfl_xor_sync(0xffffffff, ped[r][hh], 2);
        }

    if (NH == 4) {
        if (q == 0) {
#pragma unroll
            for (int r = 0; r < 4; r++) {
                int row = row0 + wrow + (r >> 1) * 16 + g + (r & 1) * 8;
                if (row < M) {
                    int hb = (n0w / 32);
                    es_out[row * 4 + hb]     = pes[r][0];
                    es_out[row * 4 + hb + 1] = pes[r][1];
                    ed_out[row * 4 + hb]     = ped[r][0];
                    ed_out[row * 4 + hb + 1] = ped[r][1];
                }
            }
        }
    } else {
        if ((w & 1) && q == 0) {
#pragma unroll
            for (int r = 0; r < 4; r++) {
                int lr = wrow + (r >> 1) * 16 + g + (r & 1) * 8;
                sm_es[lr] = pes[r][0];
                sm_ed[lr] = ped[r][0];
            }
        }
        __syncthreads();
        if (!(w & 1) && q == 0) {
#pragma unroll
            for (int r = 0; r < 4; r++) {
                int lr = wrow + (r >> 1) * 16 + g + (r & 1) * 8;
                int row = row0 + lr;
                if (row < M) {
                    es_out[row] = pes[r][0] + sm_es[lr];
                    ed_out[row] = ped[r][0] + sm_ed[lr];
                }
            }
        }
    }
}

// ---------------- gather-based message passes (round-10 proven bodies) -------
// Layer 1: warp per dst node; lane l owns cols 4l..4l+3; unroll-2 direct loads.
__global__ void msg1_k(const float* __restrict__ b1, int node0, int node1) {
    int d = node0 + ((blockIdx.x * blockDim.x + threadIdx.x) >> 5);
    int l = threadIdx.x & 31;
    if (d >= node1) return;
    int h = l >> 3;
    const float* es = (const float*)g_es1;
    float edh = ((const float*)&g_ed1[d])[h];
    int start = g_rowptr[d];
    int end = start + g_cnt[d];

    float4 acc;
    float den;
    {
        float w = __expf(lrelu(es[4 * d + h] + edh));
        uint2 u = ((const uint2*)(g_h1h + (size_t)d * F1))[l];
        float2 f01 = __half22float2(*(__half2*)&u.x);
        float2 f23 = __half22float2(*(__half2*)&u.y);
        acc.x = w * f01.x; acc.y = w * f01.y; acc.z = w * f23.x; acc.w = w * f23.y;
        den = w;
    }
    int e = start;
    for (; e + 1 < end; e += 2) {
        int s0 = g_csrc[e], s1 = g_csrc[e + 1];
        float w0 = __expf(lrelu(es[4 * s0 + h] + edh));
        float w1 = __expf(lrelu(es[4 * s1 + h] + edh));
        uint2 u0 = ((const uint2*)(g_h1h + (size_t)s0 * F1))[l];
        uint2 u1 = ((const uint2*)(g_h1h + (size_t)s1 * F1))[l];
        float2 a01 = __half22float2(*(__half2*)&u0.x);
        float2 a23 = __half22float2(*(__half2*)&u0.y);
        float2 b01 = __half22float2(*(__half2*)&u1.x);
        float2 b23 = __half22float2(*(__half2*)&u1.y);
        acc.x += w0 * a01.x + w1 * b01.x;
        acc.y += w0 * a01.y + w1 * b01.y;
        acc.z += w0 * a23.x + w1 * b23.x;
        acc.w += w0 * a23.y + w1 * b23.y;
        den += w0 + w1;
    }
    if (e < end) {
        int s = g_csrc[e];
        float w = __expf(lrelu(es[4 * s + h] + edh));
        uint2 u = ((const uint2*)(g_h1h + (size_t)s * F1))[l];
        float2 f01 = __half22float2(*(__half2*)&u.x);
        float2 f23 = __half22float2(*(__half2*)&u.y);
        acc.x += w * f01.x; acc.y += w * f01.y; acc.z += w * f23.x; acc.w += w * f23.y;
        den += w;
    }
    float inv = 1.f / (den + 1e-16f);
    const float4 bb = ((const float4*)b1)[l];
    float4 o;
    o.x = acc.x * inv + bb.x;
    o.y = acc.y * inv + bb.y;
    o.z = acc.z * inv + bb.z;
    o.w = acc.w * inv + bb.w;
    o.x = o.x > 0.f ? o.x : expm1f(o.x);
    o.y = o.y > 0.f ? o.y : expm1f(o.y);
    o.z = o.z > 0.f ? o.z : expm1f(o.z);
    o.w = o.w > 0.f ? o.w : expm1f(o.w);
    ((float4*)(g_agg1 + (size_t)d * F1))[l] = o;
}

// Layer 2: warp per dst node; lane l owns cols 2l, 2l+1.
__global__ void msg2_k(float* __restrict__ out, const float* __restrict__ b2) {
    int d = (blockIdx.x * blockDim.x + threadIdx.x) >> 5;
    int l = threadIdx.x & 31;
    if (d >= Nn) return;
    float edh = g_ed2[d];
    int start = g_rowptr[d];
    int end = start + g_cnt[d];

    float2 acc;
    float den;
    {
        float w = __expf(lrelu(g_es2[d] + edh));
        float2 v = __half22float2(((const __half2*)(g_h2h + (size_t)d * OUTF))[l]);
        acc.x = w * v.x; acc.y = w * v.y;
        den = w;
    }
    int e = start;
    for (; e + 1 < end; e += 2) {
        int s0 = g_csrc[e], s1 = g_csrc[e + 1];
        float w0 = __expf(lrelu(g_es2[s0] + edh));
        float w1 = __expf(lrelu(g_es2[s1] + edh));
        float2 v0 = __half22float2(((const __half2*)(g_h2h + (size_t)s0 * OUTF))[l]);
        float2 v1 = __half22float2(((const __half2*)(g_h2h + (size_t)s1 * OUTF))[l]);
        acc.x += w0 * v0.x + w1 * v1.x;
        acc.y += w0 * v0.y + w1 * v1.y;
        den += w0 + w1;
    }
    if (e < end) {
        int s = g_csrc[e];
        float w = __expf(lrelu(g_es2[s] + edh));
        float2 v = __half22float2(((const __half2*)(g_h2h + (size_t)s * OUTF))[l]);
        acc.x += w * v.x; acc.y += w * v.y;
        den += w;
    }
    float inv = 1.f / (den + 1e-16f);
    const float2 bb = ((const float2*)b2)[l];
    float2 o;
    o.x = acc.x * inv + bb.x;
    o.y = acc.y * inv + bb.y;
    ((float2*)(out + (size_t)d * OUTF))[l] = o;
}

// ---------------- launch ----------------------------------------------------
extern "C" void kernel_launch(void* const* d_in, const int* in_sizes, int n_in,
                              void* d_out, int out_size) {
    const float* x   = (const float*)d_in[0];
    const int*   ei  = (const int*)d_in[1];
    const float* W1  = (const float*)d_in[2];
    const float* as1 = (const float*)d_in[3];
    const float* ad1 = (const float*)d_in[4];
    const float* b1  = (const float*)d_in[5];
    const float* W2  = (const float*)d_in[6];
    const float* as2 = (const float*)d_in[7];
    const float* ad2 = (const float*)d_in[8];
    const float* b2  = (const float*)d_in[9];
    float* out = (float*)d_out;

    static cudaStream_t s1;
    static cudaEvent_t ev0, evCSR, evA, evB, evG2;
    static bool inited = false;
    static float *p_agg1, *p_es1, *p_ed1, *p_es2, *p_ed2;
    static __half *p_h1h, *p_h2h;
    static __nv_bfloat16 *pW1h, *pW1l, *pW2h, *pW2l;
    static int *p_cnt;
    if (!inited) {
        cudaStreamCreateWithFlags(&s1, cudaStreamNonBlocking);
        cudaEventCreateWithFlags(&ev0,   cudaEventDisableTiming);
        cudaEventCreateWithFlags(&evCSR, cudaEventDisableTiming);
        cudaEventCreateWithFlags(&evA,   cudaEventDisableTiming);
        cudaEventCreateWithFlags(&evB,   cudaEventDisableTiming);
        cudaEventCreateWithFlags(&evG2,  cudaEventDisableTiming);
        cudaGetSymbolAddress((void**)&p_h1h,  g_h1h);
        cudaGetSymbolAddress((void**)&p_agg1, g_agg1);
        cudaGetSymbolAddress((void**)&p_h2h,  g_h2h);
        cudaGetSymbolAddress((void**)&p_es1,  g_es1);
        cudaGetSymbolAddress((void**)&p_ed1,  g_ed1);
        cudaGetSymbolAddress((void**)&p_es2,  g_es2);
        cudaGetSymbolAddress((void**)&p_ed2,  g_ed2);
        cudaGetSymbolAddress((void**)&pW1h,   g_Wt1_hi);
        cudaGetSymbolAddress((void**)&pW1l,   g_Wt1_lo);
        cudaGetSymbolAddress((void**)&pW2h,   g_Wt2_hi);
        cudaGetSymbolAddress((void**)&pW2l,   g_Wt2_lo);
        cudaGetSymbolAddress((void**)&p_cnt,  g_cnt);
        inited = true;
    }

    // fork: CSR build chain + W2 prep on s1, concurrent with GEMM1 path
    cudaEventRecord(ev0, 0);
    cudaStreamWaitEvent(s1, ev0, 0);

    k_detect<<<1, 256, 0, s1>>>((const unsigned int*)ei);
    cudaMemsetAsync(p_cnt, 0, Nn * sizeof(int), s1);
    k_prepW2<<<(128 * 64 + 255) / 256, 256, 0, s1>>>(W2);
    k_convert_hist<<<(Ee + 255) / 256, 256, 0, s1>>>(ei);
    k_scan_block<<<NB, 1024, 0, s1>>>();
    k_scan_top<<<1, 128, 0, s1>>>();
    k_scan_add<<<(Nn + 255) / 256, 256, 0, s1>>>();
    k_fill<<<(Ee + 255) / 256, 256, 0, s1>>>();
    cudaEventRecord(evCSR, s1);

    // stream 0: W1 prep + layer-1 GEMM (scores fused)
    k_prepW1<<<(128 * 128 + 255) / 256, 256>>>(W1);
    gemm_tc<128, 4><<<(Nn + 127) / 128, 256>>>(x, pW1h, pW1l, p_h1h, Nn, 0,
                                               as1, ad1, p_es1, p_ed1);

    // join: msg1 needs CSR
    cudaStreamWaitEvent(0, evCSR, 0);

    // pipelined msg1 / gemm2 halves: gemm2_A (s1) overlaps msg1_B (s0)
    msg1_k<<<(HALF * 32 + 255) / 256, 256>>>(b1, 0, HALF);
    cudaEventRecord(evA, 0);
    cudaStreamWaitEvent(s1, evA, 0);
    gemm_tc<64, 1><<<HALF / 128, 256, 0, s1>>>(p_agg1, pW2h, pW2l, p_h2h, HALF, 0,
                                               as2, ad2, p_es2, p_ed2);

    msg1_k<<<((Nn - HALF) * 32 + 255) / 256, 256>>>(b1, HALF, Nn);
    cudaEventRecord(evB, 0);
    cudaStreamWaitEvent(s1, evB, 0);
    gemm_tc<64, 1><<<(Nn - HALF + 127) / 128, 256, 0, s1>>>(p_agg1, pW2h, pW2l, p_h2h, Nn, HALF,
                                                            as2, ad2, p_es2, p_ed2);
    cudaEventRecord(evG2, s1);
    cudaStreamWaitEvent(0, evG2, 0);

    msg2_k<<<(Nn * 32 + 255) / 256, 256>>>(out, b2);
}

// round 14
// speedup vs baseline: 1.0001x; 1.0001x over previous
#include <cuda_runtime.h>
#include <cuda_bf16.h>
#include <cuda_fp16.h>
#include <cstdint>

#define Nn   100000
#define Ee   1600000
#define F1   128                // HEADS*HID
#define OUTF 64
#define NEG_SLOPE 0.2f
#define NB   ((Nn + 1023) / 1024)   // scan blocks
#define HALF 50048                  // 391 * 128, pipeline split point

// ---------------- scratch (static device globals; no allocation) ------------
__device__ __align__(16) __half g_h1h[Nn * F1];     // layer1 features (fp16)
__device__ __align__(16) float  g_agg1[Nn * F1];    // layer1 out (fp32, GEMM2 input)
__device__ __align__(16) __half g_h2h[Nn * OUTF];   // layer2 features (fp16)
__device__ float4 g_es1[Nn], g_ed1[Nn];
__device__ float  g_es2[Nn], g_ed2[Nn];
__device__ int    g_src[Ee], g_dst[Ee];
__device__ int    g_cnt[Nn];
__device__ int    g_rowptr[Nn];
__device__ int    g_woff[Nn];
__device__ int    g_bsum[NB], g_boff[NB];
__device__ int    g_csrc[Ee];
__device__ int    g_is64;
__device__ __align__(16) __nv_bfloat16 g_Wt1_hi[128 * 128], g_Wt1_lo[128 * 128];
__device__ __align__(16) __nv_bfloat16 g_Wt2_hi[64 * 128],  g_Wt2_lo[64 * 128];

// ---------------- helpers ---------------------------------------------------
__device__ __forceinline__ float lrelu(float x) { return x > 0.f ? x : NEG_SLOPE * x; }

__device__ __forceinline__ void mma_bf16(float c[4], uint32_t a0, uint32_t a1,
                                         uint32_t a2, uint32_t a3,
                                         uint32_t b0, uint32_t b1) {
    asm volatile("mma.sync.aligned.m16n8k16.row.col.f32.bf16.bf16.f32 "
                 "{%0,%1,%2,%3}, {%4,%5,%6,%7}, {%8,%9}, {%0,%1,%2,%3};"
                 : "+f"(c[0]), "+f"(c[1]), "+f"(c[2]), "+f"(c[3])
                 : "r"(a0), "r"(a1), "r"(a2), "r"(a3), "r"(b0), "r"(b1));
}

__device__ __forceinline__ void ldsm4(uint32_t r[4], uint32_t addr) {
    asm volatile("ldmatrix.sync.aligned.m8n8.x4.shared.b16 {%0,%1,%2,%3}, [%4];"
                 : "=r"(r[0]), "=r"(r[1]), "=r"(r[2]), "=r"(r[3]) : "r"(addr));
}

// ---------------- dtype detection (parallel) ---------------------------------
__global__ void k_detect(const unsigned int* __restrict__ w) {
    __shared__ int bad;
    if (threadIdx.x == 0) bad = 0;
    __syncthreads();
    for (int j = threadIdx.x; j < 1024; j += 256)
        if (w[1 + 2 * j] != 0u) bad = 1;
    __syncthreads();
    if (threadIdx.x == 0) g_is64 = !bad;
}

__global__ void k_convert_hist(const int* __restrict__ ei) {
    int i = blockIdx.x * blockDim.x + threadIdx.x;
    if (i >= Ee) return;
    int s, d;
    if (g_is64) { s = ei[2 * i]; d = ei[2 * (Ee + i)]; }
    else        { s = ei[i];     d = ei[Ee + i]; }
    s = min(max(s, 0), Nn - 1);
    d = min(max(d, 0), Nn - 1);
    g_src[i] = s;
    g_dst[i] = d;
    atomicAdd(&g_cnt[d], 1);
}

// ---------------- CSR build --------------------------------------------------
__global__ void k_scan_block() {
    __shared__ int sh[1024];
    int t = threadIdx.x;
    int idx = blockIdx.x * 1024 + t;
    int v = (idx < Nn) ? g_cnt[idx] : 0;
    sh[t] = v;
    __syncthreads();
    for (int o = 1; o < 1024; o <<= 1) {
        int add = (t >= o) ? sh[t - o] : 0;
        __syncthreads();
        sh[t] += add;
        __syncthreads();
    }
    if (idx < Nn) g_rowptr[idx] = sh[t] - v;
    if (t == 1023) g_bsum[blockIdx.x] = sh[1023];
}

__global__ void k_scan_top() {          // 1 block x 128 threads, NB <= 128
    int t = threadIdx.x;
    int lane = t & 31, w = t >> 5;
    int v = (t < NB) ? g_bsum[t] : 0;
    int x = v;
#pragma unroll
    for (int o = 1; o < 32; o <<= 1) {
        int y = __shfl_up_sync(0xffffffff, x, o);
        if (lane >= o) x += y;
    }
    __shared__ int ws[4];
    if (lane == 31) ws[w] = x;
    __syncthreads();
    int add = 0;
    for (int i = 0; i < w; i++) add += ws[i];
    if (t < NB) g_boff[t] = x + add - v;   // exclusive
}

__global__ void k_scan_add() {
    int i = blockIdx.x * blockDim.x + threadIdx.x;
    if (i >= Nn) return;
    int r = g_rowptr[i] + g_boff[i >> 10];
    g_rowptr[i] = r;
    g_woff[i] = r;
}

__global__ void k_fill() {
    int i = blockIdx.x * blockDim.x + threadIdx.x;
    if (i >= Ee) return;
    int d = g_dst[i];
    int pos = atomicAdd(&g_woff[d], 1);
    g_csrc[pos] = g_src[i];
}

// ---------------- weight preconversion (transposed bf16 hi/lo) ---------------
__global__ void k_prepW1(const float* __restrict__ W1) {
    int i = blockIdx.x * blockDim.x + threadIdx.x;
    if (i < 128 * 128) {
        int k = i >> 7, n = i & 127;
        float v = W1[i];
        __nv_bfloat16 hi = __float2bfloat16(v);
        g_Wt1_hi[n * 128 + k] = hi;
        g_Wt1_lo[n * 128 + k] = __float2bfloat16(v - __bfloat162float(hi));
    }
}

__global__ void k_prepW2(const float* __restrict__ W2) {
    int i = blockIdx.x * blockDim.x + threadIdx.x;
    if (i < 128 * 64) {
        int k = i / 64, n = i % 64;
        float v = W2[i];
        __nv_bfloat16 hi = __float2bfloat16(v);
        g_Wt2_hi[n * 128 + k] = hi;
        g_Wt2_lo[n * 128 + k] = __float2bfloat16(v - __bfloat162float(hi));
    }
}

// ---------------- bf16 split-K TC GEMM (ldmatrix) with fused scores ----------
template<int BN, int NH>
__global__ void __launch_bounds__(256, 2)
gemm_tc(const float* __restrict__ A,
        const __nv_bfloat16* __restrict__ Bt_hi,
        const __nv_bfloat16* __restrict__ Bt_lo,
        __half* __restrict__ C, int M, int row_start,
        const float* __restrict__ a_src, const float* __restrict__ a_dst,
        float* __restrict__ es_out, float* __restrict__ ed_out) {
    constexpr int K  = 128;
    constexpr int BK = 32;
    constexpr int AP = 40;
    constexpr int NBW = BN / 16;

    __shared__ __nv_bfloat16 As_hi[128 * AP], As_lo[128 * AP];
    __shared__ __nv_bfloat16 Bs_hi[BN * AP],  Bs_lo[BN * AP];
    __shared__ float sm_es[128], sm_ed[128];

    const int tid  = threadIdx.x;
    const int w    = tid >> 5;
    const int lane = tid & 31;
    const int g    = lane >> 2;
    const int q    = lane & 3;
    const int wrow = (w >> 1) * 32;
    const int n0w  = (w & 1) * (BN / 2);
    const int row0 = row_start + blockIdx.x * 128;

    const int a_r = lane & 15;
    const int a_k = (lane >> 4) * 8;
    const int b_r = (lane & 7) + ((lane >> 4) * 8);
    const int b_k = ((lane >> 3) & 1) * 8;

    const uint32_t sAhi = (uint32_t)__cvta_generic_to_shared(As_hi);
    const uint32_t sAlo = (uint32_t)__cvta_generic_to_shared(As_lo);
    const uint32_t sBhi = (uint32_t)__cvta_generic_to_shared(Bs_hi);
    const uint32_t sBlo = (uint32_t)__cvta_generic_to_shared(Bs_lo);

    float c[2][NBW][4];
#pragma unroll
    for (int m = 0; m < 2; m++)
#pragma unroll
        for (int nb = 0; nb < NBW; nb++)
#pragma unroll
            for (int j = 0; j < 4; j++) c[m][nb][j] = 0.f;

    for (int kt = 0; kt < K; kt += BK) {
        __syncthreads();
#pragma unroll
        for (int it = 0; it < 4; it++) {
            int i = tid + it * 256;
            int row = i >> 3, kq = i & 7;
            int gr = row0 + row;
            float4 v = make_float4(0.f, 0.f, 0.f, 0.f);
            if (gr < M) v = *(const float4*)(A + (size_t)gr * K + kt + kq * 4);
            int base = row * AP + kq * 4;
            __nv_bfloat16 h0 = __float2bfloat16(v.x), h1b = __float2bfloat16(v.y);
            __nv_bfloat16 h2 = __float2bfloat16(v.z), h3 = __float2bfloat16(v.w);
            *(__nv_bfloat162*)&As_hi[base]     = __nv_bfloat162(h0, h1b);
            *(__nv_bfloat162*)&As_hi[base + 2] = __nv_bfloat162(h2, h3);
            *(__nv_bfloat162*)&As_lo[base] = __nv_bfloat162(
                __float2bfloat16(v.x - __bfloat162float(h0)),
                __float2bfloat16(v.y - __bfloat162float(h1b)));
            *(__nv_bfloat162*)&As_lo[base + 2] = __nv_bfloat162(
                __float2bfloat16(v.z - __bfloat162float(h2)),
                __float2bfloat16(v.w - __bfloat162float(h3)));
        }
#pragma unroll
        for (int it = 0; it < BN * 4 / 256; it++) {
            int i = tid + it * 256;
            int n = i >> 2, j = i & 3;
            *(uint4*)&Bs_hi[n * AP + j * 8] =
                *(const uint4*)&Bt_hi[n * 128 + kt + j * 8];
            *(uint4*)&Bs_lo[n * AP + j * 8] =
                *(const uint4*)&Bt_lo[n * 128 + kt + j * 8];
        }
        __syncthreads();

#pragma unroll
        for (int kk = 0; kk < BK; kk += 16) {
            uint32_t ahi[2][4], alo[2][4];
#pragma unroll
            for (int m = 0; m < 2; m++) {
                uint32_t off = ((wrow + m * 16 + a_r) * AP + kk + a_k) * 2;
                ldsm4(ahi[m], sAhi + off);
                ldsm4(alo[m], sAlo + off);
            }
#pragma unroll
            for (int nbp = 0; nbp < NBW / 2; nbp++) {
                int nb = 2 * nbp;
                uint32_t off = ((n0w + nb * 8 + b_r) * AP + kk + b_k) * 2;
                uint32_t bh[4], bl[4];
                ldsm4(bh, sBhi + off);
                ldsm4(bl, sBlo + off);
#pragma unroll
                for (int m = 0; m < 2; m++) {
                    mma_bf16(c[m][nb],     ahi[m][0], ahi[m][1], ahi[m][2], ahi[m][3], bh[0], bh[1]);
                    mma_bf16(c[m][nb],     ahi[m][0], ahi[m][1], ahi[m][2], ahi[m][3], bl[0], bl[1]);
                    mma_bf16(c[m][nb],     alo[m][0], alo[m][1], alo[m][2], alo[m][3], bh[0], bh[1]);
                    mma_bf16(c[m][nb + 1], ahi[m][0], ahi[m][1], ahi[m][2], ahi[m][3], bh[2], bh[3]);
                    mma_bf16(c[m][nb + 1], ahi[m][0], ahi[m][1], ahi[m][2], ahi[m][3], bl[2], bl[3]);
                    mma_bf16(c[m][nb + 1], alo[m][0], alo[m][1], alo[m][2], alo[m][3], bh[2], bh[3]);
                }
            }
        }
    }

    // ---- C store (fp16) ----
#pragma unroll
    for (int m = 0; m < 2; m++) {
#pragma unroll
        for (int nb = 0; nb < NBW; nb++) {
            int row = row0 + wrow + m * 16 + g;
            int col = n0w + nb * 8 + 2 * q;
            if (row < M)
                *(__half2*)(C + (size_t)row * BN + col) =
                    __floats2half2_rn(c[m][nb][0], c[m][nb][1]);
            if (row + 8 < M)
                *(__half2*)(C + (size_t)(row + 8) * BN + col) =
                    __floats2half2_rn(c[m][nb][2], c[m][nb][3]);
        }
    }

    // ---- fused score epilogue (fp32 fragments) ----
    constexpr int HW = (NH == 4) ? 2 : 1;
    float pes[4][HW], ped[4][HW];
#pragma unroll
    for (int r = 0; r < 4; r++)
#pragma unroll
        for (int hh = 0; hh < HW; hh++) { pes[r][hh] = 0.f; ped[r][hh] = 0.f; }
#pragma unroll
    for (int nb = 0; nb < NBW; nb++) {
        int colg = n0w + nb * 8 + 2 * q;
        float a0s = a_src[colg], a1s = a_src[colg + 1];
        float a0d = a_dst[colg], a1d = a_dst[colg + 1];
        int hh = (NH == 4) ? (nb / (NBW / 2)) : 0;
#pragma unroll
        for (int m = 0; m < 2; m++) {
            pes[m * 2 + 0][hh] += c[m][nb][0] * a0s + c[m][nb][1] * a1s;
            pes[m * 2 + 1][hh] += c[m][nb][2] * a0s + c[m][nb][3] * a1s;
            ped[m * 2 + 0][hh] += c[m][nb][0] * a0d + c[m][nb][1] * a1d;
            ped[m * 2 + 1][hh] += c[m][nb][2] * a0d + c[m][nb][3] * a1d;
        }
    }
#pragma unroll
    for (int r = 0; r < 4; r++)
#pragma unroll
        for (int hh = 0; hh < HW; hh++) {
            pes[r][hh] += __shfl_xor_sync(0xffffffff, pes[r][hh], 1);
            pes[r][hh] += __shfl_xor_sync(0xffffffff, pes[r][hh], 2);
            ped[r][hh] += __shfl_xor_sync(0xffffffff, ped[r][hh], 1);
            ped[r][hh] += __shfl_xor_sync(0xffffffff, ped[r][hh], 2);
        }

    if (NH == 4) {
        if (q == 0) {
#pragma unroll
            for (int r = 0; r < 4; r++) {
                int row = row0 + wrow + (r >> 1) * 16 + g + (r & 1) * 8;
                if (row < M) {
                    int hb = (n0w / 32);
                    es_out[row * 4 + hb]     = pes[r][0];
                    es_out[row * 4 + hb + 1] = pes[r][1];
                    ed_out[row * 4 + hb]     = ped[r][0];
                    ed_out[row * 4 + hb + 1] = ped[r][1];
                }
            }
        }
    } else {
        if ((w & 1) && q == 0) {
#pragma unroll
            for (int r = 0; r < 4; r++) {
                int lr = wrow + (r >> 1) * 16 + g + (r & 1) * 8;
                sm_es[lr] = pes[r][0];
                sm_ed[lr] = ped[r][0];
            }
        }
        __syncthreads();
        if (!(w & 1) && q == 0) {
#pragma unroll
            for (int r = 0; r < 4; r++) {
                int lr = wrow + (r >> 1) * 16 + g + (r & 1) * 8;
                int row = row0 + lr;
                if (row < M) {
                    es_out[row] = pes[r][0] + sm_es[lr];
                    ed_out[row] = ped[r][0] + sm_ed[lr];
                }
            }
        }
    }
}

// ---------------- gather-based message passes (round-10 proven bodies) -------
// Layer 1: warp per dst node; lane l owns cols 4l..4l+3; unroll-2 direct loads.
__global__ void msg1_k(const float* __restrict__ b1, int node0, int node1) {
    int d = node0 + ((blockIdx.x * blockDim.x + threadIdx.x) >> 5);
    int l = threadIdx.x & 31;
    if (d >= node1) return;
    int h = l >> 3;
    const float* es = (const float*)g_es1;
    float edh = ((const float*)&g_ed1[d])[h];
    int start = g_rowptr[d];
    int end = start + g_cnt[d];

    float4 acc;
    float den;
    {
        float w = __expf(lrelu(es[4 * d + h] + edh));
        uint2 u = ((const uint2*)(g_h1h + (size_t)d * F1))[l];
        float2 f01 = __half22float2(*(__half2*)&u.x);
        float2 f23 = __half22float2(*(__half2*)&u.y);
        acc.x = w * f01.x; acc.y = w * f01.y; acc.z = w * f23.x; acc.w = w * f23.y;
        den = w;
    }
    int e = start;
    for (; e + 1 < end; e += 2) {
        int s0 = g_csrc[e], s1 = g_csrc[e + 1];
        float w0 = __expf(lrelu(es[4 * s0 + h] + edh));
        float w1 = __expf(lrelu(es[4 * s1 + h] + edh));
        uint2 u0 = ((const uint2*)(g_h1h + (size_t)s0 * F1))[l];
        uint2 u1 = ((const uint2*)(g_h1h + (size_t)s1 * F1))[l];
        float2 a01 = __half22float2(*(__half2*)&u0.x);
        float2 a23 = __half22float2(*(__half2*)&u0.y);
        float2 b01 = __half22float2(*(__half2*)&u1.x);
        float2 b23 = __half22float2(*(__half2*)&u1.y);
        acc.x += w0 * a01.x + w1 * b01.x;
        acc.y += w0 * a01.y + w1 * b01.y;
        acc.z += w0 * a23.x + w1 * b23.x;
        acc.w += w0 * a23.y + w1 * b23.y;
        den += w0 + w1;
    }
    if (e < end) {
        int s = g_csrc[e];
        float w = __expf(lrelu(es[4 * s + h] + edh));
        uint2 u = ((const uint2*)(g_h1h + (size_t)s * F1))[l];
        float2 f01 = __half22float2(*(__half2*)&u.x);
        float2 f23 = __half22float2(*(__half2*)&u.y);
        acc.x += w * f01.x; acc.y += w * f01.y; acc.z += w * f23.x; acc.w += w * f23.y;
        den += w;
    }
    float inv = 1.f / (den + 1e-16f);
    const float4 bb = ((const float4*)b1)[l];
    float4 o;
    o.x = acc.x * inv + bb.x;
    o.y = acc.y * inv + bb.y;
    o.z = acc.z * inv + bb.z;
    o.w = acc.w * inv + bb.w;
    o.x = o.x > 0.f ? o.x : expm1f(o.x);
    o.y = o.y > 0.f ? o.y : expm1f(o.y);
    o.z = o.z > 0.f ? o.z : expm1f(o.z);
    o.w = o.w > 0.f ? o.w : expm1f(o.w);
    ((float4*)(g_agg1 + (size_t)d * F1))[l] = o;
}

// Layer 2: warp per dst node; lane l owns cols 2l, 2l+1.
__global__ void msg2_k(float* __restrict__ out, const float* __restrict__ b2) {
    int d = (blockIdx.x * blockDim.x + threadIdx.x) >> 5;
    int l = threadIdx.x & 31;
    if (d >= Nn) return;
    float edh = g_ed2[d];
    int start = g_rowptr[d];
    int end = start + g_cnt[d];

    float2 acc;
    float den;
    {
        float w = __expf(lrelu(g_es2[d] + edh));
        float2 v = __half22float2(((const __half2*)(g_h2h + (size_t)d * OUTF))[l]);
        acc.x = w * v.x; acc.y = w * v.y;
        den = w;
    }
    int e = start;
    for (; e + 1 < end; e += 2) {
        int s0 = g_csrc[e], s1 = g_csrc[e + 1];
        float w0 = __expf(lrelu(g_es2[s0] + edh));
        float w1 = __expf(lrelu(g_es2[s1] + edh));
        float2 v0 = __half22float2(((const __half2*)(g_h2h + (size_t)s0 * OUTF))[l]);
        float2 v1 = __half22float2(((const __half2*)(g_h2h + (size_t)s1 * OUTF))[l]);
        acc.x += w0 * v0.x + w1 * v1.x;
        acc.y += w0 * v0.y + w1 * v1.y;
        den += w0 + w1;
    }
    if (e < end) {
        int s = g_csrc[e];
        float w = __expf(lrelu(g_es2[s] + edh));
        float2 v = __half22float2(((const __half2*)(g_h2h + (size_t)s * OUTF))[l]);
        acc.x += w * v.x; acc.y += w * v.y;
        den += w;
    }
    float inv = 1.f / (den + 1e-16f);
    const float2 bb = ((const float2*)b2)[l];
    float2 o;
    o.x = acc.x * inv + bb.x;
    o.y = acc.y * inv + bb.y;
    ((float2*)(out + (size_t)d * OUTF))[l] = o;
}

// ---------------- launch ----------------------------------------------------
extern "C" void kernel_launch(void* const* d_in, const int* in_sizes, int n_in,
                              void* d_out, int out_size) {
    const float* x   = (const float*)d_in[0];
    const int*   ei  = (const int*)d_in[1];
    const float* W1  = (const float*)d_in[2];
    const float* as1 = (const float*)d_in[3];
    const float* ad1 = (const float*)d_in[4];
    const float* b1  = (const float*)d_in[5];
    const float* W2  = (const float*)d_in[6];
    const float* as2 = (const float*)d_in[7];
    const float* ad2 = (const float*)d_in[8];
    const float* b2  = (const float*)d_in[9];
    float* out = (float*)d_out;

    static cudaStream_t s1;
    static cudaEvent_t ev0, evCSR, evA, evB, evG2;
    static bool inited = false;
    static float *p_agg1, *p_es1, *p_ed1, *p_es2, *p_ed2;
    static __half *p_h1h, *p_h2h;
    static __nv_bfloat16 *pW1h, *pW1l, *pW2h, *pW2l;
    static int *p_cnt;
    if (!inited) {
        cudaStreamCreateWithFlags(&s1, cudaStreamNonBlocking);
        cudaEventCreateWithFlags(&ev0,   cudaEventDisableTiming);
        cudaEventCreateWithFlags(&evCSR, cudaEventDisableTiming);
        cudaEventCreateWithFlags(&evA,   cudaEventDisableTiming);
        cudaEventCreateWithFlags(&evB,   cudaEventDisableTiming);
        cudaEventCreateWithFlags(&evG2,  cudaEventDisableTiming);
        cudaGetSymbolAddress((void**)&p_h1h,  g_h1h);
        cudaGetSymbolAddress((void**)&p_agg1, g_agg1);
        cudaGetSymbolAddress((void**)&p_h2h,  g_h2h);
        cudaGetSymbolAddress((void**)&p_es1,  g_es1);
        cudaGetSymbolAddress((void**)&p_ed1,  g_ed1);
        cudaGetSymbolAddress((void**)&p_es2,  g_es2);
        cudaGetSymbolAddress((void**)&p_ed2,  g_ed2);
        cudaGetSymbolAddress((void**)&pW1h,   g_Wt1_hi);
        cudaGetSymbolAddress((void**)&pW1l,   g_Wt1_lo);
        cudaGetSymbolAddress((void**)&pW2h,   g_Wt2_hi);
        cudaGetSymbolAddress((void**)&pW2l,   g_Wt2_lo);
        cudaGetSymbolAddress((void**)&p_cnt,  g_cnt);
        inited = true;
    }

    // fork: CSR build chain + W2 prep on s1, concurrent with GEMM1 path
    cudaEventRecord(ev0, 0);
    cudaStreamWaitEvent(s1, ev0, 0);

    k_detect<<<1, 256, 0, s1>>>((const unsigned int*)ei);
    cudaMemsetAsync(p_cnt, 0, Nn * sizeof(int), s1);
    k_prepW2<<<(128 * 64 + 255) / 256, 256, 0, s1>>>(W2);
    k_convert_hist<<<(Ee + 255) / 256, 256, 0, s1>>>(ei);
    k_scan_block<<<NB, 1024, 0, s1>>>();
    k_scan_top<<<1, 128, 0, s1>>>();
    k_scan_add<<<(Nn + 255) / 256, 256, 0, s1>>>();
    k_fill<<<(Ee + 255) / 256, 256, 0, s1>>>();
    cudaEventRecord(evCSR, s1);

    // stream 0: W1 prep + layer-1 GEMM (scores fused)
    k_prepW1<<<(128 * 128 + 255) / 256, 256>>>(W1);
    gemm_tc<128, 4><<<(Nn + 127) / 128, 256>>>(x, pW1h, pW1l, p_h1h, Nn, 0,
                                               as1, ad1, p_es1, p_ed1);

    // join: msg1 needs CSR
    cudaStreamWaitEvent(0, evCSR, 0);

    // pipelined msg1 / gemm2 halves: gemm2_A (s1) overlaps msg1_B (s0)
    msg1_k<<<(HALF * 32 + 255) / 256, 256>>>(b1, 0, HALF);
    cudaEventRecord(evA, 0);
    cudaStreamWaitEvent(s1, evA, 0);
    gemm_tc<64, 1><<<HALF / 128, 256, 0, s1>>>(p_agg1, pW2h, pW2l, p_h2h, HALF, 0,
                                               as2, ad2, p_es2, p_ed2);

    msg1_k<<<((Nn - HALF) * 32 + 255) / 256, 256>>>(b1, HALF, Nn);
    cudaEventRecord(evB, 0);
    cudaStreamWaitEvent(s1, evB, 0);
    gemm_tc<64, 1><<<(Nn - HALF + 127) / 128, 256, 0, s1>>>(p_agg1, pW2h, pW2l, p_h2h, Nn, HALF,
                                                            as2, ad2, p_es2, p_ed2);
    cudaEventRecord(evG2, s1);
    cudaStreamWaitEvent(0, evG2, 0);

    msg2_k<<<(Nn * 32 + 255) / 256, 256>>>(out, b2);
}

// round 15
// speedup vs baseline: 1.0003x; 1.0001x over previous
#include <cuda_runtime.h>
#include <cuda_bf16.h>
#include <cuda_fp16.h>
#include <cstdint>

#define Nn   100000
#define Ee   1600000
#define F1   128                // HEADS*HID
#define OUTF 64
#define NEG_SLOPE 0.2f
#define NB   ((Nn + 1023) / 1024)   // scan blocks
#define HALF 50048                  // 391 * 128, pipeline split point

// ---------------- scratch (static device globals; no allocation) ------------
__device__ __align__(16) __half g_h1h[Nn * F1];     // layer1 features (fp16)
__device__ __align__(16) float  g_agg1[Nn * F1];    // layer1 out (fp32, GEMM2 input)
__device__ __align__(16) __half g_h2h[Nn * OUTF];   // layer2 features (fp16)
__device__ float4 g_es1[Nn], g_ed1[Nn];
__device__ float  g_es2[Nn], g_ed2[Nn];
__device__ int    g_src[Ee], g_dst[Ee];
__device__ int    g_cnt[Nn];
__device__ int    g_rowptr[Nn];
__device__ int    g_woff[Nn];
__device__ int    g_bsum[NB], g_boff[NB];
__device__ int    g_csrc[Ee];
__device__ int    g_is64;
__device__ __align__(16) __nv_bfloat16 g_Wt1_hi[128 * 128], g_Wt1_lo[128 * 128];
__device__ __align__(16) __nv_bfloat16 g_Wt2_hi[64 * 128],  g_Wt2_lo[64 * 128];

// ---------------- helpers ---------------------------------------------------
__device__ __forceinline__ float lrelu(float x) { return x > 0.f ? x : NEG_SLOPE * x; }

__device__ __forceinline__ void mma_bf16(float c[4], uint32_t a0, uint32_t a1,
                                         uint32_t a2, uint32_t a3,
                                         uint32_t b0, uint32_t b1) {
    asm volatile("mma.sync.aligned.m16n8k16.row.col.f32.bf16.bf16.f32 "
                 "{%0,%1,%2,%3}, {%4,%5,%6,%7}, {%8,%9}, {%0,%1,%2,%3};"
                 : "+f"(c[0]), "+f"(c[1]), "+f"(c[2]), "+f"(c[3])
                 : "r"(a0), "r"(a1), "r"(a2), "r"(a3), "r"(b0), "r"(b1));
}

__device__ __forceinline__ void ldsm4(uint32_t r[4], uint32_t addr) {
    asm volatile("ldmatrix.sync.aligned.m8n8.x4.shared.b16 {%0,%1,%2,%3}, [%4];"
                 : "=r"(r[0]), "=r"(r[1]), "=r"(r[2]), "=r"(r[3]) : "r"(addr));
}

// ---------------- dtype detection (parallel) ---------------------------------
__global__ void k_detect(const unsigned int* __restrict__ w) {
    __shared__ int bad;
    if (threadIdx.x == 0) bad = 0;
    __syncthreads();
    for (int j = threadIdx.x; j < 1024; j += 256)
        if (w[1 + 2 * j] != 0u) bad = 1;
    __syncthreads();
    if (threadIdx.x == 0) g_is64 = !bad;
}

__global__ void k_convert_hist(const int* __restrict__ ei) {
    int i = blockIdx.x * blockDim.x + threadIdx.x;
    if (i >= Ee) return;
    int s, d;
    if (g_is64) { s = ei[2 * i]; d = ei[2 * (Ee + i)]; }
    else        { s = ei[i];     d = ei[Ee + i]; }
    s = min(max(s, 0), Nn - 1);
    d = min(max(d, 0), Nn - 1);
    g_src[i] = s;
    g_dst[i] = d;
    atomicAdd(&g_cnt[d], 1);
}

// ---------------- CSR build --------------------------------------------------
__global__ void k_scan_block() {
    __shared__ int sh[1024];
    int t = threadIdx.x;
    int idx = blockIdx.x * 1024 + t;
    int v = (idx < Nn) ? g_cnt[idx] : 0;
    sh[t] = v;
    __syncthreads();
    for (int o = 1; o < 1024; o <<= 1) {
        int add = (t >= o) ? sh[t - o] : 0;
        __syncthreads();
        sh[t] += add;
        __syncthreads();
    }
    if (idx < Nn) g_rowptr[idx] = sh[t] - v;
    if (t == 1023) g_bsum[blockIdx.x] = sh[1023];
}

__global__ void k_scan_top() {          // 1 block x 128 threads, NB <= 128
    int t = threadIdx.x;
    int lane = t & 31, w = t >> 5;
    int v = (t < NB) ? g_bsum[t] : 0;
    int x = v;
#pragma unroll
    for (int o = 1; o < 32; o <<= 1) {
        int y = __shfl_up_sync(0xffffffff, x, o);
        if (lane >= o) x += y;
    }
    __shared__ int ws[4];
    if (lane == 31) ws[w] = x;
    __syncthreads();
    int add = 0;
    for (int i = 0; i < w; i++) add += ws[i];
    if (t < NB) g_boff[t] = x + add - v;   // exclusive
}

__global__ void k_scan_add() {
    int i = blockIdx.x * blockDim.x + threadIdx.x;
    if (i >= Nn) return;
    int r = g_rowptr[i] + g_boff[i >> 10];
    g_rowptr[i] = r;
    g_woff[i] = r;
}

__global__ void k_fill() {
    int i = blockIdx.x * blockDim.x + threadIdx.x;
    if (i >= Ee) return;
    int d = g_dst[i];
    int pos = atomicAdd(&g_woff[d], 1);
    g_csrc[pos] = g_src[i];
}

// ---------------- weight preconversion (transposed bf16 hi/lo) ---------------
__global__ void k_prepW1(const float* __restrict__ W1) {
    int i = blockIdx.x * blockDim.x + threadIdx.x;
    if (i < 128 * 128) {
        int k = i >> 7, n = i & 127;
        float v = W1[i];
        __nv_bfloat16 hi = __float2bfloat16(v);
        g_Wt1_hi[n * 128 + k] = hi;
        g_Wt1_lo[n * 128 + k] = __float2bfloat16(v - __bfloat162float(hi));
    }
}

__global__ void k_prepW2(const float* __restrict__ W2) {
    int i = blockIdx.x * blockDim.x + threadIdx.x;
    if (i < 128 * 64) {
        int k = i / 64, n = i % 64;
        float v = W2[i];
        __nv_bfloat16 hi = __float2bfloat16(v);
        g_Wt2_hi[n * 128 + k] = hi;
        g_Wt2_lo[n * 128 + k] = __float2bfloat16(v - __bfloat162float(hi));
    }
}

// ---------------- bf16 split-K TC GEMM (ldmatrix) with fused scores ----------
template<int BN, int NH>
__global__ void __launch_bounds__(256, 2)
gemm_tc(const float* __restrict__ A,
        const __nv_bfloat16* __restrict__ Bt_hi,
        const __nv_bfloat16* __restrict__ Bt_lo,
        __half* __restrict__ C, int M, int row_start,
        const float* __restrict__ a_src, const float* __restrict__ a_dst,
        float* __restrict__ es_out, float* __restrict__ ed_out) {
    constexpr int K  = 128;
    constexpr int BK = 32;
    constexpr int AP = 40;
    constexpr int NBW = BN / 16;

    __shared__ __nv_bfloat16 As_hi[128 * AP], As_lo[128 * AP];
    __shared__ __nv_bfloat16 Bs_hi[BN * AP],  Bs_lo[BN * AP];
    __shared__ float sm_es[128], sm_ed[128];

    const int tid  = threadIdx.x;
    const int w    = tid >> 5;
    const int lane = tid & 31;
    const int g    = lane >> 2;
    const int q    = lane & 3;
    const int wrow = (w >> 1) * 32;
    const int n0w  = (w & 1) * (BN / 2);
    const int row0 = row_start + blockIdx.x * 128;

    const int a_r = lane & 15;
    const int a_k = (lane >> 4) * 8;
    const int b_r = (lane & 7) + ((lane >> 4) * 8);
    const int b_k = ((lane >> 3) & 1) * 8;

    const uint32_t sAhi = (uint32_t)__cvta_generic_to_shared(As_hi);
    const uint32_t sAlo = (uint32_t)__cvta_generic_to_shared(As_lo);
    const uint32_t sBhi = (uint32_t)__cvta_generic_to_shared(Bs_hi);
    const uint32_t sBlo = (uint32_t)__cvta_generic_to_shared(Bs_lo);

    float c[2][NBW][4];
#pragma unroll
    for (int m = 0; m < 2; m++)
#pragma unroll
        for (int nb = 0; nb < NBW; nb++)
#pragma unroll
            for (int j = 0; j < 4; j++) c[m][nb][j] = 0.f;

    for (int kt = 0; kt < K; kt += BK) {
        __syncthreads();
#pragma unroll
        for (int it = 0; it < 4; it++) {
            int i = tid + it * 256;
            int row = i >> 3, kq = i & 7;
            int gr = row0 + row;
            float4 v = make_float4(0.f, 0.f, 0.f, 0.f);
            if (gr < M) v = *(const float4*)(A + (size_t)gr * K + kt + kq * 4);
            int base = row * AP + kq * 4;
            __nv_bfloat16 h0 = __float2bfloat16(v.x), h1b = __float2bfloat16(v.y);
            __nv_bfloat16 h2 = __float2bfloat16(v.z), h3 = __float2bfloat16(v.w);
            *(__nv_bfloat162*)&As_hi[base]     = __nv_bfloat162(h0, h1b);
            *(__nv_bfloat162*)&As_hi[base + 2] = __nv_bfloat162(h2, h3);
            *(__nv_bfloat162*)&As_lo[base] = __nv_bfloat162(
                __float2bfloat16(v.x - __bfloat162float(h0)),
                __float2bfloat16(v.y - __bfloat162float(h1b)));
            *(__nv_bfloat162*)&As_lo[base + 2] = __nv_bfloat162(
                __float2bfloat16(v.z - __bfloat162float(h2)),
                __float2bfloat16(v.w - __bfloat162float(h3)));
        }
#pragma unroll
        for (int it = 0; it < BN * 4 / 256; it++) {
            int i = tid + it * 256;
            int n = i >> 2, j = i & 3;
            *(uint4*)&Bs_hi[n * AP + j * 8] =
                *(const uint4*)&Bt_hi[n * 128 + kt + j * 8];
            *(uint4*)&Bs_lo[n * AP + j * 8] =
                *(const uint4*)&Bt_lo[n * 128 + kt + j * 8];
        }
        __syncthreads();

#pragma unroll
        for (int kk = 0; kk < BK; kk += 16) {
            uint32_t ahi[2][4], alo[2][4];
#pragma unroll
            for (int m = 0; m < 2; m++) {
                uint32_t off = ((wrow + m * 16 + a_r) * AP + kk + a_k) * 2;
                ldsm4(ahi[m], sAhi + off);
                ldsm4(alo[m], sAlo + off);
            }
#pragma unroll
            for (int nbp = 0; nbp < NBW / 2; nbp++) {
                int nb = 2 * nbp;
                uint32_t off = ((n0w + nb * 8 + b_r) * AP + kk + b_k) * 2;
                uint32_t bh[4], bl[4];
                ldsm4(bh, sBhi + off);
                ldsm4(bl, sBlo + off);
#pragma unroll
                for (int m = 0; m < 2; m++) {
                    mma_bf16(c[m][nb],     ahi[m][0], ahi[m][1], ahi[m][2], ahi[m][3], bh[0], bh[1]);
                    mma_bf16(c[m][nb],     ahi[m][0], ahi[m][1], ahi[m][2], ahi[m][3], bl[0], bl[1]);
                    mma_bf16(c[m][nb],     alo[m][0], alo[m][1], alo[m][2], alo[m][3], bh[0], bh[1]);
                    mma_bf16(c[m][nb + 1], ahi[m][0], ahi[m][1], ahi[m][2], ahi[m][3], bh[2], bh[3]);
                    mma_bf16(c[m][nb + 1], ahi[m][0], ahi[m][1], ahi[m][2], ahi[m][3], bl[2], bl[3]);
                    mma_bf16(c[m][nb + 1], alo[m][0], alo[m][1], alo[m][2], alo[m][3], bh[2], bh[3]);
                }
            }
        }
    }

    // ---- C store (fp16) ----
#pragma unroll
    for (int m = 0; m < 2; m++) {
#pragma unroll
        for (int nb = 0; nb < NBW; nb++) {
            int row = row0 + wrow + m * 16 + g;
            int col = n0w + nb * 8 + 2 * q;
            if (row < M)
                *(__half2*)(C + (size_t)row * BN + col) =
                    __floats2half2_rn(c[m][nb][0], c[m][nb][1]);
            if (row + 8 < M)
                *(__half2*)(C + (size_t)(row + 8) * BN + col) =
                    __floats2half2_rn(c[m][nb][2], c[m][nb][3]);
        }
    }

    // ---- fused score epilogue (fp32 fragments) ----
    constexpr int HW = (NH == 4) ? 2 : 1;
    float pes[4][HW], ped[4][HW];
#pragma unroll
    for (int r = 0; r < 4; r++)
#pragma unroll
        for (int hh = 0; hh < HW; hh++) { pes[r][hh] = 0.f; ped[r][hh] = 0.f; }
#pragma unroll
    for (int nb = 0; nb < NBW; nb++) {
        int colg = n0w + nb * 8 + 2 * q;
        float a0s = a_src[colg], a1s = a_src[colg + 1];
        float a0d = a_dst[colg], a1d = a_dst[colg + 1];
        int hh = (NH == 4) ? (nb / (NBW / 2)) : 0;
#pragma unroll
        for (int m = 0; m < 2; m++) {
            pes[m * 2 + 0][hh] += c[m][nb][0] * a0s + c[m][nb][1] * a1s;
            pes[m * 2 + 1][hh] += c[m][nb][2] * a0s + c[m][nb][3] * a1s;
            ped[m * 2 + 0][hh] += c[m][nb][0] * a0d + c[m][nb][1] * a1d;
            ped[m * 2 + 1][hh] += c[m][nb][2] * a0d + c[m][nb][3] * a1d;
        }
    }
#pragma unroll
    for (int r = 0; r < 4; r++)
#pragma unroll
        for (int hh = 0; hh < HW; hh++) {
            pes[r][hh] += __shfl_xor_sync(0xffffffff, pes[r][hh], 1);
            pes[r][hh] += __shfl_xor_sync(0xffffffff, pes[r][hh], 2);
            ped[r][hh] += __shfl_xor_sync(0xffffffff, ped[r][hh], 1);
            ped[r][hh] += __shfl_xor_sync(0xffffffff, ped[r][hh], 2);
        }

    if (NH == 4) {
        if (q == 0) {
#pragma unroll
            for (int r = 0; r < 4; r++) {
                int row = row0 + wrow + (r >> 1) * 16 + g + (r & 1) * 8;
                if (row < M) {
                    int hb = (n0w / 32);
                    es_out[row * 4 + hb]     = pes[r][0];
                    es_out[row * 4 + hb + 1] = pes[r][1];
                    ed_out[row * 4 + hb]     = ped[r][0];
                    ed_out[row * 4 + hb + 1] = ped[r][1];
                }
            }
        }
    } else {
        if ((w & 1) && q == 0) {
#pragma unroll
            for (int r = 0; r < 4; r++) {
                int lr = wrow + (r >> 1) * 16 + g + (r & 1) * 8;
                sm_es[lr] = pes[r][0];
                sm_ed[lr] = ped[r][0];
            }
        }
        __syncthreads();
        if (!(w & 1) && q == 0) {
#pragma unroll
            for (int r = 0; r < 4; r++) {
                int lr = wrow + (r >> 1) * 16 + g + (r & 1) * 8;
                int row = row0 + lr;
                if (row < M) {
                    es_out[row] = pes[r][0] + sm_es[lr];
                    ed_out[row] = ped[r][0] + sm_ed[lr];
                }
            }
        }
    }
}

// ---------------- gather-based message passes (round-10 proven bodies) -------
// Layer 1: warp per dst node; lane l owns cols 4l..4l+3; unroll-2 direct loads.
__global__ void msg1_k(const float* __restrict__ b1, int node0, int node1) {
    int d = node0 + ((blockIdx.x * blockDim.x + threadIdx.x) >> 5);
    int l = threadIdx.x & 31;
    if (d >= node1) return;
    int h = l >> 3;
    const float* es = (const float*)g_es1;
    float edh = ((const float*)&g_ed1[d])[h];
    int start = g_rowptr[d];
    int end = start + g_cnt[d];

    float4 acc;
    float den;
    {
        float w = __expf(lrelu(es[4 * d + h] + edh));
        uint2 u = ((const uint2*)(g_h1h + (size_t)d * F1))[l];
        float2 f01 = __half22float2(*(__half2*)&u.x);
        float2 f23 = __half22float2(*(__half2*)&u.y);
        acc.x = w * f01.x; acc.y = w * f01.y; acc.z = w * f23.x; acc.w = w * f23.y;
        den = w;
    }
    int e = start;
    for (; e + 1 < end; e += 2) {
        int s0 = g_csrc[e], s1 = g_csrc[e + 1];
        float w0 = __expf(lrelu(es[4 * s0 + h] + edh));
        float w1 = __expf(lrelu(es[4 * s1 + h] + edh));
        uint2 u0 = ((const uint2*)(g_h1h + (size_t)s0 * F1))[l];
        uint2 u1 = ((const uint2*)(g_h1h + (size_t)s1 * F1))[l];
        float2 a01 = __half22float2(*(__half2*)&u0.x);
        float2 a23 = __half22float2(*(__half2*)&u0.y);
        float2 b01 = __half22float2(*(__half2*)&u1.x);
        float2 b23 = __half22float2(*(__half2*)&u1.y);
        acc.x += w0 * a01.x + w1 * b01.x;
        acc.y += w0 * a01.y + w1 * b01.y;
        acc.z += w0 * a23.x + w1 * b23.x;
        acc.w += w0 * a23.y + w1 * b23.y;
        den += w0 + w1;
    }
    if (e < end) {
        int s = g_csrc[e];
        float w = __expf(lrelu(es[4 * s + h] + edh));
        uint2 u = ((const uint2*)(g_h1h + (size_t)s * F1))[l];
        float2 f01 = __half22float2(*(__half2*)&u.x);
        float2 f23 = __half22float2(*(__half2*)&u.y);
        acc.x += w * f01.x; acc.y += w * f01.y; acc.z += w * f23.x; acc.w += w * f23.y;
        den += w;
    }
    float inv = 1.f / (den + 1e-16f);
    const float4 bb = ((const float4*)b1)[l];
    float4 o;
    o.x = acc.x * inv + bb.x;
    o.y = acc.y * inv + bb.y;
    o.z = acc.z * inv + bb.z;
    o.w = acc.w * inv + bb.w;
    o.x = o.x > 0.f ? o.x : expm1f(o.x);
    o.y = o.y > 0.f ? o.y : expm1f(o.y);
    o.z = o.z > 0.f ? o.z : expm1f(o.z);
    o.w = o.w > 0.f ? o.w : expm1f(o.w);
    ((float4*)(g_agg1 + (size_t)d * F1))[l] = o;
}

// Layer 2: warp per dst node; lane l owns cols 2l, 2l+1.
__global__ void msg2_k(float* __restrict__ out, const float* __restrict__ b2) {
    int d = (blockIdx.x * blockDim.x + threadIdx.x) >> 5;
    int l = threadIdx.x & 31;
    if (d >= Nn) return;
    float edh = g_ed2[d];
    int start = g_rowptr[d];
    int end = start + g_cnt[d];

    float2 acc;
    float den;
    {
        float w = __expf(lrelu(g_es2[d] + edh));
        float2 v = __half22float2(((const __half2*)(g_h2h + (size_t)d * OUTF))[l]);
        acc.x = w * v.x; acc.y = w * v.y;
        den = w;
    }
    int e = start;
    for (; e + 1 < end; e += 2) {
        int s0 = g_csrc[e], s1 = g_csrc[e + 1];
        float w0 = __expf(lrelu(g_es2[s0] + edh));
        float w1 = __expf(lrelu(g_es2[s1] + edh));
        float2 v0 = __half22float2(((const __half2*)(g_h2h + (size_t)s0 * OUTF))[l]);
        float2 v1 = __half22float2(((const __half2*)(g_h2h + (size_t)s1 * OUTF))[l]);
        acc.x += w0 * v0.x + w1 * v1.x;
        acc.y += w0 * v0.y + w1 * v1.y;
        den += w0 + w1;
    }
    if (e < end) {
        int s = g_csrc[e];
        float w = __expf(lrelu(g_es2[s] + edh));
        float2 v = __half22float2(((const __half2*)(g_h2h + (size_t)s * OUTF))[l]);
        acc.x += w * v.x; acc.y += w * v.y;
        den += w;
    }
    float inv = 1.f / (den + 1e-16f);
    const float2 bb = ((const float2*)b2)[l];
    float2 o;
    o.x = acc.x * inv + bb.x;
    o.y = acc.y * inv + bb.y;
    ((float2*)(out + (size_t)d * OUTF))[l] = o;
}

// ---------------- launch ----------------------------------------------------
extern "C" void kernel_launch(void* const* d_in, const int* in_sizes, int n_in,
                              void* d_out, int out_size) {
    const float* x   = (const float*)d_in[0];
    const int*   ei  = (const int*)d_in[1];
    const float* W1  = (const float*)d_in[2];
    const float* as1 = (const float*)d_in[3];
    const float* ad1 = (const float*)d_in[4];
    const float* b1  = (const float*)d_in[5];
    const float* W2  = (const float*)d_in[6];
    const float* as2 = (const float*)d_in[7];
    const float* ad2 = (const float*)d_in[8];
    const float* b2  = (const float*)d_in[9];
    float* out = (float*)d_out;

    static cudaStream_t s1;
    static cudaEvent_t ev0, evCSR, evA, evB, evG2;
    static bool inited = false;
    static float *p_agg1, *p_es1, *p_ed1, *p_es2, *p_ed2;
    static __half *p_h1h, *p_h2h;
    static __nv_bfloat16 *pW1h, *pW1l, *pW2h, *pW2l;
    static int *p_cnt;
    if (!inited) {
        cudaStreamCreateWithFlags(&s1, cudaStreamNonBlocking);
        cudaEventCreateWithFlags(&ev0,   cudaEventDisableTiming);
        cudaEventCreateWithFlags(&evCSR, cudaEventDisableTiming);
        cudaEventCreateWithFlags(&evA,   cudaEventDisableTiming);
        cudaEventCreateWithFlags(&evB,   cudaEventDisableTiming);
        cudaEventCreateWithFlags(&evG2,  cudaEventDisableTiming);
        cudaGetSymbolAddress((void**)&p_h1h,  g_h1h);
        cudaGetSymbolAddress((void**)&p_agg1, g_agg1);
        cudaGetSymbolAddress((void**)&p_h2h,  g_h2h);
        cudaGetSymbolAddress((void**)&p_es1,  g_es1);
        cudaGetSymbolAddress((void**)&p_ed1,  g_ed1);
        cudaGetSymbolAddress((void**)&p_es2,  g_es2);
        cudaGetSymbolAddress((void**)&p_ed2,  g_ed2);
        cudaGetSymbolAddress((void**)&pW1h,   g_Wt1_hi);
        cudaGetSymbolAddress((void**)&pW1l,   g_Wt1_lo);
        cudaGetSymbolAddress((void**)&pW2h,   g_Wt2_hi);
        cudaGetSymbolAddress((void**)&pW2l,   g_Wt2_lo);
        cudaGetSymbolAddress((void**)&p_cnt,  g_cnt);
        inited = true;
    }

    // fork: CSR build chain + W2 prep on s1, concurrent with GEMM1 path
    cudaEventRecord(ev0, 0);
    cudaStreamWaitEvent(s1, ev0, 0);

    k_detect<<<1, 256, 0, s1>>>((const unsigned int*)ei);
    cudaMemsetAsync(p_cnt, 0, Nn * sizeof(int), s1);
    k_prepW2<<<(128 * 64 + 255) / 256, 256, 0, s1>>>(W2);
    k_convert_hist<<<(Ee + 255) / 256, 256, 0, s1>>>(ei);
    k_scan_block<<<NB, 1024, 0, s1>>>();
    k_scan_top<<<1, 128, 0, s1>>>();
    k_scan_add<<<(Nn + 255) / 256, 256, 0, s1>>>();
    k_fill<<<(Ee + 255) / 256, 256, 0, s1>>>();
    cudaEventRecord(evCSR, s1);

    // stream 0: W1 prep + layer-1 GEMM (scores fused)
    k_prepW1<<<(128 * 128 + 255) / 256, 256>>>(W1);
    gemm_tc<128, 4><<<(Nn + 127) / 128, 256>>>(x, pW1h, pW1l, p_h1h, Nn, 0,
                                               as1, ad1, p_es1, p_ed1);

    // join: msg1 needs CSR
    cudaStreamWaitEvent(0, evCSR, 0);

    // pipelined msg1 / gemm2 halves: gemm2_A (s1) overlaps msg1_B (s0)
    msg1_k<<<(HALF * 32 + 255) / 256, 256>>>(b1, 0, HALF);
    cudaEventRecord(evA, 0);
    cudaStreamWaitEvent(s1, evA, 0);
    gemm_tc<64, 1><<<HALF / 128, 256, 0, s1>>>(p_agg1, pW2h, pW2l, p_h2h, HALF, 0,
                                               as2, ad2, p_es2, p_ed2);

    msg1_k<<<((Nn - HALF) * 32 + 255) / 256, 256>>>(b1, HALF, Nn);
    cudaEventRecord(evB, 0);
    cudaStreamWaitEvent(s1, evB, 0);
    gemm_tc<64, 1><<<(Nn - HALF + 127) / 128, 256, 0, s1>>>(p_agg1, pW2h, pW2l, p_h2h, Nn, HALF,
                                                            as2, ad2, p_es2, p_ed2);
    cudaEventRecord(evG2, s1);
    cudaStreamWaitEvent(0, evG2, 0);

    msg2_k<<<(Nn * 32 + 255) / 256, 256>>>(out, b2);
}

// round 16
// speedup vs baseline: 1.0004x; 1.0001x over previous
#include <cuda_runtime.h>
#include <cuda_bf16.h>
#include <cuda_fp16.h>
#include <cstdint>

#define Nn   100000
#define Ee   1600000
#define F1   128                // HEADS*HID
#define OUTF 64
#define NEG_SLOPE 0.2f
#define NB   ((Nn + 1023) / 1024)   // scan blocks
#define HALF 50048                  // 391 * 128, pipeline split point

// ---------------- scratch (static device globals; no allocation) ------------
__device__ __align__(16) __half g_h1h[Nn * F1];     // layer1 features (fp16)
__device__ __align__(16) float  g_agg1[Nn * F1];    // layer1 out (fp32, GEMM2 input)
__device__ __align__(16) __half g_h2h[Nn * OUTF];   // layer2 features (fp16)
__device__ float4 g_es1[Nn], g_ed1[Nn];
__device__ float  g_es2[Nn], g_ed2[Nn];
__device__ int    g_src[Ee], g_dst[Ee];
__device__ int    g_cnt[Nn];
__device__ int    g_rowptr[Nn];
__device__ int    g_woff[Nn];
__device__ int    g_bsum[NB], g_boff[NB];
__device__ int    g_csrc[Ee];
__device__ int    g_is64;
__device__ __align__(16) __nv_bfloat16 g_Wt1_hi[128 * 128], g_Wt1_lo[128 * 128];
__device__ __align__(16) __nv_bfloat16 g_Wt2_hi[64 * 128],  g_Wt2_lo[64 * 128];

// ---------------- helpers ---------------------------------------------------
__device__ __forceinline__ float lrelu(float x) { return x > 0.f ? x : NEG_SLOPE * x; }

__device__ __forceinline__ void mma_bf16(float c[4], uint32_t a0, uint32_t a1,
                                         uint32_t a2, uint32_t a3,
                                         uint32_t b0, uint32_t b1) {
    asm volatile("mma.sync.aligned.m16n8k16.row.col.f32.bf16.bf16.f32 "
                 "{%0,%1,%2,%3}, {%4,%5,%6,%7}, {%8,%9}, {%0,%1,%2,%3};"
                 : "+f"(c[0]), "+f"(c[1]), "+f"(c[2]), "+f"(c[3])
                 : "r"(a0), "r"(a1), "r"(a2), "r"(a3), "r"(b0), "r"(b1));
}

__device__ __forceinline__ void ldsm4(uint32_t r[4], uint32_t addr) {
    asm volatile("ldmatrix.sync.aligned.m8n8.x4.shared.b16 {%0,%1,%2,%3}, [%4];"
                 : "=r"(r[0]), "=r"(r[1]), "=r"(r[2]), "=r"(r[3]) : "r"(addr));
}

// ---------------- dtype detection (parallel) ---------------------------------
__global__ void k_detect(const unsigned int* __restrict__ w) {
    __shared__ int bad;
    if (threadIdx.x == 0) bad = 0;
    __syncthreads();
    for (int j = threadIdx.x; j < 1024; j += 256)
        if (w[1 + 2 * j] != 0u) bad = 1;
    __syncthreads();
    if (threadIdx.x == 0) g_is64 = !bad;
}

__global__ void k_convert_hist(const int* __restrict__ ei) {
    int i = blockIdx.x * blockDim.x + threadIdx.x;
    if (i >= Ee) return;
    int s, d;
    if (g_is64) { s = ei[2 * i]; d = ei[2 * (Ee + i)]; }
    else        { s = ei[i];     d = ei[Ee + i]; }
    s = min(max(s, 0), Nn - 1);
    d = min(max(d, 0), Nn - 1);
    g_src[i] = s;
    g_dst[i] = d;
    atomicAdd(&g_cnt[d], 1);
}

// ---------------- CSR build --------------------------------------------------
__global__ void k_scan_block() {
    __shared__ int sh[1024];
    int t = threadIdx.x;
    int idx = blockIdx.x * 1024 + t;
    int v = (idx < Nn) ? g_cnt[idx] : 0;
    sh[t] = v;
    __syncthreads();
    for (int o = 1; o < 1024; o <<= 1) {
        int add = (t >= o) ? sh[t - o] : 0;
        __syncthreads();
        sh[t] += add;
        __syncthreads();
    }
    if (idx < Nn) g_rowptr[idx] = sh[t] - v;
    if (t == 1023) g_bsum[blockIdx.x] = sh[1023];
}

__global__ void k_scan_top() {          // 1 block x 128 threads, NB <= 128
    int t = threadIdx.x;
    int lane = t & 31, w = t >> 5;
    int v = (t < NB) ? g_bsum[t] : 0;
    int x = v;
#pragma unroll
    for (int o = 1; o < 32; o <<= 1) {
        int y = __shfl_up_sync(0xffffffff, x, o);
        if (lane >= o) x += y;
    }
    __shared__ int ws[4];
    if (lane == 31) ws[w] = x;
    __syncthreads();
    int add = 0;
    for (int i = 0; i < w; i++) add += ws[i];
    if (t < NB) g_boff[t] = x + add - v;   // exclusive
}

__global__ void k_scan_add() {
    int i = blockIdx.x * blockDim.x + threadIdx.x;
    if (i >= Nn) return;
    int r = g_rowptr[i] + g_boff[i >> 10];
    g_rowptr[i] = r;
    g_woff[i] = r;
}

__global__ void k_fill() {
    int i = blockIdx.x * blockDim.x + threadIdx.x;
    if (i >= Ee) return;
    int d = g_dst[i];
    int pos = atomicAdd(&g_woff[d], 1);
    g_csrc[pos] = g_src[i];
}

// ---------------- weight preconversion (transposed bf16 hi/lo) ---------------
__global__ void k_prepW1(const float* __restrict__ W1) {
    int i = blockIdx.x * blockDim.x + threadIdx.x;
    if (i < 128 * 128) {
        int k = i >> 7, n = i & 127;
        float v = W1[i];
        __nv_bfloat16 hi = __float2bfloat16(v);
        g_Wt1_hi[n * 128 + k] = hi;
        g_Wt1_lo[n * 128 + k] = __float2bfloat16(v - __bfloat162float(hi));
    }
}

__global__ void k_prepW2(const float* __restrict__ W2) {
    int i = blockIdx.x * blockDim.x + threadIdx.x;
    if (i < 128 * 64) {
        int k = i / 64, n = i % 64;
        float v = W2[i];
        __nv_bfloat16 hi = __float2bfloat16(v);
        g_Wt2_hi[n * 128 + k] = hi;
        g_Wt2_lo[n * 128 + k] = __float2bfloat16(v - __bfloat162float(hi));
    }
}

// ---------------- bf16 split-K TC GEMM (ldmatrix) with fused scores ----------
template<int BN, int NH>
__global__ void __launch_bounds__(256, 2)
gemm_tc(const float* __restrict__ A,
        const __nv_bfloat16* __restrict__ Bt_hi,
        const __nv_bfloat16* __restrict__ Bt_lo,
        __half* __restrict__ C, int M, int row_start,
        const float* __restrict__ a_src, const float* __restrict__ a_dst,
        float* __restrict__ es_out, float* __restrict__ ed_out) {
    constexpr int K  = 128;
    constexpr int BK = 32;
    constexpr int AP = 40;
    constexpr int NBW = BN / 16;

    __shared__ __nv_bfloat16 As_hi[128 * AP], As_lo[128 * AP];
    __shared__ __nv_bfloat16 Bs_hi[BN * AP],  Bs_lo[BN * AP];
    __shared__ float sm_es[128], sm_ed[128];

    const int tid  = threadIdx.x;
    const int w    = tid >> 5;
    const int lane = tid & 31;
    const int g    = lane >> 2;
    const int q    = lane & 3;
    const int wrow = (w >> 1) * 32;
    const int n0w  = (w & 1) * (BN / 2);
    const int row0 = row_start + blockIdx.x * 128;

    const int a_r = lane & 15;
    const int a_k = (lane >> 4) * 8;
    const int b_r = (lane & 7) + ((lane >> 4) * 8);
    const int b_k = ((lane >> 3) & 1) * 8;

    const uint32_t sAhi = (uint32_t)__cvta_generic_to_shared(As_hi);
    const uint32_t sAlo = (uint32_t)__cvta_generic_to_shared(As_lo);
    const uint32_t sBhi = (uint32_t)__cvta_generic_to_shared(Bs_hi);
    const uint32_t sBlo = (uint32_t)__cvta_generic_to_shared(Bs_lo);

    float c[2][NBW][4];
#pragma unroll
    for (int m = 0; m < 2; m++)
#pragma unroll
        for (int nb = 0; nb < NBW; nb++)
#pragma unroll
            for (int j = 0; j < 4; j++) c[m][nb][j] = 0.f;

    for (int kt = 0; kt < K; kt += BK) {
        __syncthreads();
#pragma unroll
        for (int it = 0; it < 4; it++) {
            int i = tid + it * 256;
            int row = i >> 3, kq = i & 7;
            int gr = row0 + row;
            float4 v = make_float4(0.f, 0.f, 0.f, 0.f);
            if (gr < M) v = *(const float4*)(A + (size_t)gr * K + kt + kq * 4);
            int base = row * AP + kq * 4;
            __nv_bfloat16 h0 = __float2bfloat16(v.x), h1b = __float2bfloat16(v.y);
            __nv_bfloat16 h2 = __float2bfloat16(v.z), h3 = __float2bfloat16(v.w);
            *(__nv_bfloat162*)&As_hi[base]     = __nv_bfloat162(h0, h1b);
            *(__nv_bfloat162*)&As_hi[base + 2] = __nv_bfloat162(h2, h3);
            *(__nv_bfloat162*)&As_lo[base] = __nv_bfloat162(
                __float2bfloat16(v.x - __bfloat162float(h0)),
                __float2bfloat16(v.y - __bfloat162float(h1b)));
            *(__nv_bfloat162*)&As_lo[base + 2] = __nv_bfloat162(
                __float2bfloat16(v.z - __bfloat162float(h2)),
                __float2bfloat16(v.w - __bfloat162float(h3)));
        }
#pragma unroll
        for (int it = 0; it < BN * 4 / 256; it++) {
            int i = tid + it * 256;
            int n = i >> 2, j = i & 3;
            *(uint4*)&Bs_hi[n * AP + j * 8] =
                *(const uint4*)&Bt_hi[n * 128 + kt + j * 8];
            *(uint4*)&Bs_lo[n * AP + j * 8] =
                *(const uint4*)&Bt_lo[n * 128 + kt + j * 8];
        }
        __syncthreads();

#pragma unroll
        for (int kk = 0; kk < BK; kk += 16) {
            uint32_t ahi[2][4], alo[2][4];
#pragma unroll
            for (int m = 0; m < 2; m++) {
                uint32_t off = ((wrow + m * 16 + a_r) * AP + kk + a_k) * 2;
                ldsm4(ahi[m], sAhi + off);
                ldsm4(alo[m], sAlo + off);
            }
#pragma unroll
            for (int nbp = 0; nbp < NBW / 2; nbp++) {
                int nb = 2 * nbp;
                uint32_t off = ((n0w + nb * 8 + b_r) * AP + kk + b_k) * 2;
                uint32_t bh[4], bl[4];
                ldsm4(bh, sBhi + off);
                ldsm4(bl, sBlo + off);
#pragma unroll
                for (int m = 0; m < 2; m++) {
                    mma_bf16(c[m][nb],     ahi[m][0], ahi[m][1], ahi[m][2], ahi[m][3], bh[0], bh[1]);
                    mma_bf16(c[m][nb],     ahi[m][0], ahi[m][1], ahi[m][2], ahi[m][3], bl[0], bl[1]);
                    mma_bf16(c[m][nb],     alo[m][0], alo[m][1], alo[m][2], alo[m][3], bh[0], bh[1]);
                    mma_bf16(c[m][nb + 1], ahi[m][0], ahi[m][1], ahi[m][2], ahi[m][3], bh[2], bh[3]);
                    mma_bf16(c[m][nb + 1], ahi[m][0], ahi[m][1], ahi[m][2], ahi[m][3], bl[2], bl[3]);
                    mma_bf16(c[m][nb + 1], alo[m][0], alo[m][1], alo[m][2], alo[m][3], bh[2], bh[3]);
                }
            }
        }
    }

    // ---- C store (fp16) ----
#pragma unroll
    for (int m = 0; m < 2; m++) {
#pragma unroll
        for (int nb = 0; nb < NBW; nb++) {
            int row = row0 + wrow + m * 16 + g;
            int col = n0w + nb * 8 + 2 * q;
            if (row < M)
                *(__half2*)(C + (size_t)row * BN + col) =
                    __floats2half2_rn(c[m][nb][0], c[m][nb][1]);
            if (row + 8 < M)
                *(__half2*)(C + (size_t)(row + 8) * BN + col) =
                    __floats2half2_rn(c[m][nb][2], c[m][nb][3]);
        }
    }

    // ---- fused score epilogue (fp32 fragments) ----
    constexpr int HW = (NH == 4) ? 2 : 1;
    float pes[4][HW], ped[4][HW];
#pragma unroll
    for (int r = 0; r < 4; r++)
#pragma unroll
        for (int hh = 0; hh < HW; hh++) { pes[r][hh] = 0.f; ped[r][hh] = 0.f; }
#pragma unroll
    for (int nb = 0; nb < NBW; nb++) {
        int colg = n0w + nb * 8 + 2 * q;
        float a0s = a_src[colg], a1s = a_src[colg + 1];
        float a0d = a_dst[colg], a1d = a_dst[colg + 1];
        int hh = (NH == 4) ? (nb / (NBW / 2)) : 0;
#pragma unroll
        for (int m = 0; m < 2; m++) {
            pes[m * 2 + 0][hh] += c[m][nb][0] * a0s + c[m][nb][1] * a1s;
            pes[m * 2 + 1][hh] += c[m][nb][2] * a0s + c[m][nb][3] * a1s;
            ped[m * 2 + 0][hh] += c[m][nb][0] * a0d + c[m][nb][1] * a1d;
            ped[m * 2 + 1][hh] += c[m][nb][2] * a0d + c[m][nb][3] * a1d;
        }
    }
#pragma unroll
    for (int r = 0; r < 4; r++)
#pragma unroll
        for (int hh = 0; hh < HW; hh++) {
            pes[r][hh] += __shfl_xor_sync(0xffffffff, pes[r][hh], 1);
            pes[r][hh] += __shfl_xor_sync(0xffffffff, pes[r][hh], 2);
            ped[r][hh] += __shfl_xor_sync(0xffffffff, ped[r][hh], 1);
            ped[r][hh] += __shfl_xor_sync(0xffffffff, ped[r][hh], 2);
        }

    if (NH == 4) {
        if (q == 0) {
#pragma unroll
            for (int r = 0; r < 4; r++) {
                int row = row0 + wrow + (r >> 1) * 16 + g + (r & 1) * 8;
                if (row < M) {
                    int hb = (n0w / 32);
                    es_out[row * 4 + hb]     = pes[r][0];
                    es_out[row * 4 + hb + 1] = pes[r][1];
                    ed_out[row * 4 + hb]     = ped[r][0];
                    ed_out[row * 4 + hb + 1] = ped[r][1];
                }
            }
        }
    } else {
        if ((w & 1) && q == 0) {
#pragma unroll
            for (int r = 0; r < 4; r++) {
                int lr = wrow + (r >> 1) * 16 + g + (r & 1) * 8;
                sm_es[lr] = pes[r][0];
                sm_ed[lr] = ped[r][0];
            }
        }
        __syncthreads();
        if (!(w & 1) && q == 0) {
#pragma unroll
            for (int r = 0; r < 4; r++) {
                int lr = wrow + (r >> 1) * 16 + g + (r & 1) * 8;
                int row = row0 + lr;
                if (row < M) {
                    es_out[row] = pes[r][0] + sm_es[lr];
                    ed_out[row] = ped[r][0] + sm_ed[lr];
                }
            }
        }
    }
}

// ---------------- gather-based message passes (round-10 proven bodies) -------
// Layer 1: warp per dst node; lane l owns cols 4l..4l+3; unroll-2 direct loads.
__global__ void msg1_k(const float* __restrict__ b1, int node0, int node1) {
    int d = node0 + ((blockIdx.x * blockDim.x + threadIdx.x) >> 5);
    int l = threadIdx.x & 31;
    if (d >= node1) return;
    int h = l >> 3;
    const float* es = (const float*)g_es1;
    float edh = ((const float*)&g_ed1[d])[h];
    int start = g_rowptr[d];
    int end = start + g_cnt[d];

    float4 acc;
    float den;
    {
        float w = __expf(lrelu(es[4 * d + h] + edh));
        uint2 u = ((const uint2*)(g_h1h + (size_t)d * F1))[l];
        float2 f01 = __half22float2(*(__half2*)&u.x);
        float2 f23 = __half22float2(*(__half2*)&u.y);
        acc.x = w * f01.x; acc.y = w * f01.y; acc.z = w * f23.x; acc.w = w * f23.y;
        den = w;
    }
    int e = start;
    for (; e + 1 < end; e += 2) {
        int s0 = g_csrc[e], s1 = g_csrc[e + 1];
        float w0 = __expf(lrelu(es[4 * s0 + h] + edh));
        float w1 = __expf(lrelu(es[4 * s1 + h] + edh));
        uint2 u0 = ((const uint2*)(g_h1h + (size_t)s0 * F1))[l];
        uint2 u1 = ((const uint2*)(g_h1h + (size_t)s1 * F1))[l];
        float2 a01 = __half22float2(*(__half2*)&u0.x);
        float2 a23 = __half22float2(*(__half2*)&u0.y);
        float2 b01 = __half22float2(*(__half2*)&u1.x);
        float2 b23 = __half22float2(*(__half2*)&u1.y);
        acc.x += w0 * a01.x + w1 * b01.x;
        acc.y += w0 * a01.y + w1 * b01.y;
        acc.z += w0 * a23.x + w1 * b23.x;
        acc.w += w0 * a23.y + w1 * b23.y;
        den += w0 + w1;
    }
    if (e < end) {
        int s = g_csrc[e];
        float w = __expf(lrelu(es[4 * s + h] + edh));
        uint2 u = ((const uint2*)(g_h1h + (size_t)s * F1))[l];
        float2 f01 = __half22float2(*(__half2*)&u.x);
        float2 f23 = __half22float2(*(__half2*)&u.y);
        acc.x += w * f01.x; acc.y += w * f01.y; acc.z += w * f23.x; acc.w += w * f23.y;
        den += w;
    }
    float inv = 1.f / (den + 1e-16f);
    const float4 bb = ((const float4*)b1)[l];
    float4 o;
    o.x = acc.x * inv + bb.x;
    o.y = acc.y * inv + bb.y;
    o.z = acc.z * inv + bb.z;
    o.w = acc.w * inv + bb.w;
    o.x = o.x > 0.f ? o.x : expm1f(o.x);
    o.y = o.y > 0.f ? o.y : expm1f(o.y);
    o.z = o.z > 0.f ? o.z : expm1f(o.z);
    o.w = o.w > 0.f ? o.w : expm1f(o.w);
    ((float4*)(g_agg1 + (size_t)d * F1))[l] = o;
}

// Layer 2: warp per dst node; lane l owns cols 2l, 2l+1.
__global__ void msg2_k(float* __restrict__ out, const float* __restrict__ b2) {
    int d = (blockIdx.x * blockDim.x + threadIdx.x) >> 5;
    int l = threadIdx.x & 31;
    if (d >= Nn) return;
    float edh = g_ed2[d];
    int start = g_rowptr[d];
    int end = start + g_cnt[d];

    float2 acc;
    float den;
    {
        float w = __expf(lrelu(g_es2[d] + edh));
        float2 v = __half22float2(((const __half2*)(g_h2h + (size_t)d * OUTF))[l]);
        acc.x = w * v.x; acc.y = w * v.y;
        den = w;
    }
    int e = start;
    for (; e + 1 < end; e += 2) {
        int s0 = g_csrc[e], s1 = g_csrc[e + 1];
        float w0 = __expf(lrelu(g_es2[s0] + edh));
        float w1 = __expf(lrelu(g_es2[s1] + edh));
        float2 v0 = __half22float2(((const __half2*)(g_h2h + (size_t)s0 * OUTF))[l]);
        float2 v1 = __half22float2(((const __half2*)(g_h2h + (size_t)s1 * OUTF))[l]);
        acc.x += w0 * v0.x + w1 * v1.x;
        acc.y += w0 * v0.y + w1 * v1.y;
        den += w0 + w1;
    }
    if (e < end) {
        int s = g_csrc[e];
        float w = __expf(lrelu(g_es2[s] + edh));
        float2 v = __half22float2(((const __half2*)(g_h2h + (size_t)s * OUTF))[l]);
        acc.x += w * v.x; acc.y += w * v.y;
        den += w;
    }
    float inv = 1.f / (den + 1e-16f);
    const float2 bb = ((const float2*)b2)[l];
    float2 o;
    o.x = acc.x * inv + bb.x;
    o.y = acc.y * inv + bb.y;
    ((float2*)(out + (size_t)d * OUTF))[l] = o;
}

// ---------------- launch ----------------------------------------------------
extern "C" void kernel_launch(void* const* d_in, const int* in_sizes, int n_in,
                              void* d_out, int out_size) {
    const float* x   = (const float*)d_in[0];
    const int*   ei  = (const int*)d_in[1];
    const float* W1  = (const float*)d_in[2];
    const float* as1 = (const float*)d_in[3];
    const float* ad1 = (const float*)d_in[4];
    const float* b1  = (const float*)d_in[5];
    const float* W2  = (const float*)d_in[6];
    const float* as2 = (const float*)d_in[7];
    const float* ad2 = (const float*)d_in[8];
    const float* b2  = (const float*)d_in[9];
    float* out = (float*)d_out;

    static cudaStream_t s1;
    static cudaEvent_t ev0, evCSR, evA, evB, evG2;
    static bool inited = false;
    static float *p_agg1, *p_es1, *p_ed1, *p_es2, *p_ed2;
    static __half *p_h1h, *p_h2h;
    static __nv_bfloat16 *pW1h, *pW1l, *pW2h, *pW2l;
    static int *p_cnt;
    if (!inited) {
        cudaStreamCreateWithFlags(&s1, cudaStreamNonBlocking);
        cudaEventCreateWithFlags(&ev0,   cudaEventDisableTiming);
        cudaEventCreateWithFlags(&evCSR, cudaEventDisableTiming);
        cudaEventCreateWithFlags(&evA,   cudaEventDisableTiming);
        cudaEventCreateWithFlags(&evB,   cudaEventDisableTiming);
        cudaEventCreateWithFlags(&evG2,  cudaEventDisableTiming);
        cudaGetSymbolAddress((void**)&p_h1h,  g_h1h);
        cudaGetSymbolAddress((void**)&p_agg1, g_agg1);
        cudaGetSymbolAddress((void**)&p_h2h,  g_h2h);
        cudaGetSymbolAddress((void**)&p_es1,  g_es1);
        cudaGetSymbolAddress((void**)&p_ed1,  g_ed1);
        cudaGetSymbolAddress((void**)&p_es2,  g_es2);
        cudaGetSymbolAddress((void**)&p_ed2,  g_ed2);
        cudaGetSymbolAddress((void**)&pW1h,   g_Wt1_hi);
        cudaGetSymbolAddress((void**)&pW1l,   g_Wt1_lo);
        cudaGetSymbolAddress((void**)&pW2h,   g_Wt2_hi);
        cudaGetSymbolAddress((void**)&pW2l,   g_Wt2_lo);
        cudaGetSymbolAddress((void**)&p_cnt,  g_cnt);
        inited = true;
    }

    // fork: CSR build chain + W2 prep on s1, concurrent with GEMM1 path
    cudaEventRecord(ev0, 0);
    cudaStreamWaitEvent(s1, ev0, 0);

    k_detect<<<1, 256, 0, s1>>>((const unsigned int*)ei);
    cudaMemsetAsync(p_cnt, 0, Nn * sizeof(int), s1);
    k_prepW2<<<(128 * 64 + 255) / 256, 256, 0, s1>>>(W2);
    k_convert_hist<<<(Ee + 255) / 256, 256, 0, s1>>>(ei);
    k_scan_block<<<NB, 1024, 0, s1>>>();
    k_scan_top<<<1, 128, 0, s1>>>();
    k_scan_add<<<(Nn + 255) / 256, 256, 0, s1>>>();
    k_fill<<<(Ee + 255) / 256, 256, 0, s1>>>();
    cudaEventRecord(evCSR, s1);

    // stream 0: W1 prep + layer-1 GEMM (scores fused)
    k_prepW1<<<(128 * 128 + 255) / 256, 256>>>(W1);
    gemm_tc<128, 4><<<(Nn + 127) / 128, 256>>>(x, pW1h, pW1l, p_h1h, Nn, 0,
                                               as1, ad1, p_es1, p_ed1);

    // join: msg1 needs CSR
    cudaStreamWaitEvent(0, evCSR, 0);

    // pipelined msg1 / gemm2 halves: gemm2_A (s1) overlaps msg1_B (s0)
    msg1_k<<<(HALF * 32 + 255) / 256, 256>>>(b1, 0, HALF);
    cudaEventRecord(evA, 0);
    cudaStreamWaitEvent(s1, evA, 0);
    gemm_tc<64, 1><<<HALF / 128, 256, 0, s1>>>(p_agg1, pW2h, pW2l, p_h2h, HALF, 0,
                                               as2, ad2, p_es2, p_ed2);

    msg1_k<<<((Nn - HALF) * 32 + 255) / 256, 256>>>(b1, HALF, Nn);
    cudaEventRecord(evB, 0);
    cudaStreamWaitEvent(s1, evB, 0);
    gemm_tc<64, 1><<<(Nn - HALF + 127) / 128, 256, 0, s1>>>(p_agg1, pW2h, pW2l, p_h2h, Nn, HALF,
                                                            as2, ad2, p_es2, p_ed2);
    cudaEventRecord(evG2, s1);
    cudaStreamWaitEvent(0, evG2, 0);

    msg2_k<<<(Nn * 32 + 255) / 256, 256>>>(out, b2);
}

// round 17
// speedup vs baseline: 1.0470x; 1.0465x over previous
#include <cuda_runtime.h>
#include <cuda_bf16.h>
#include <cuda_fp16.h>
#include <cstdint>

#define Nn   100000
#define Ee   1600000
#define F1   128                // HEADS*HID
#define OUTF 64
#define NEG_SLOPE 0.2f
#define NB   ((Nn + 1023) / 1024)   // scan blocks

// ---------------- scratch (static device globals; no allocation) ------------
__device__ __align__(16) __half g_h1h[Nn * F1];     // layer1 features (fp16)
__device__ __align__(16) float  g_agg1[Nn * F1];    // layer1 out (fp32, GEMM2 input)
__device__ __align__(16) __half g_h2h[Nn * OUTF];   // layer2 features (fp16)
__device__ float4 g_es1[Nn], g_ed1[Nn];
__device__ float  g_es2[Nn], g_ed2[Nn];
__device__ int    g_src[Ee], g_dst[Ee];
__device__ int    g_cnt[Nn];
__device__ int    g_rowptr[Nn];
__device__ int    g_woff[Nn];
__device__ int    g_bsum[NB], g_boff[NB];
__device__ int    g_csrc[Ee];
__device__ int    g_is64;
__device__ __align__(16) __nv_bfloat16 g_Wt1_hi[128 * 128], g_Wt1_lo[128 * 128];
__device__ __align__(16) __nv_bfloat16 g_Wt2_hi[64 * 128],  g_Wt2_lo[64 * 128];

// ---------------- helpers ---------------------------------------------------
__device__ __forceinline__ float lrelu(float x) { return x > 0.f ? x : NEG_SLOPE * x; }

__device__ __forceinline__ void mma_bf16(float c[4], uint32_t a0, uint32_t a1,
                                         uint32_t a2, uint32_t a3,
                                         uint32_t b0, uint32_t b1) {
    asm volatile("mma.sync.aligned.m16n8k16.row.col.f32.bf16.bf16.f32 "
                 "{%0,%1,%2,%3}, {%4,%5,%6,%7}, {%8,%9}, {%0,%1,%2,%3};"
                 : "+f"(c[0]), "+f"(c[1]), "+f"(c[2]), "+f"(c[3])
                 : "r"(a0), "r"(a1), "r"(a2), "r"(a3), "r"(b0), "r"(b1));
}

__device__ __forceinline__ void ldsm4(uint32_t r[4], uint32_t addr) {
    asm volatile("ldmatrix.sync.aligned.m8n8.x4.shared.b16 {%0,%1,%2,%3}, [%4];"
                 : "=r"(r[0]), "=r"(r[1]), "=r"(r[2]), "=r"(r[3]) : "r"(addr));
}

__device__ __forceinline__ void cp16(uint32_t saddr, const void* gaddr) {
    asm volatile("cp.async.cg.shared.global [%0], [%1], 16;" :: "r"(saddr), "l"(gaddr));
}

// ---------------- dtype detection (parallel) ---------------------------------
__global__ void k_detect(const unsigned int* __restrict__ w) {
    __shared__ int bad;
    if (threadIdx.x == 0) bad = 0;
    __syncthreads();
    for (int j = threadIdx.x; j < 1024; j += 256)
        if (w[1 + 2 * j] != 0u) bad = 1;
    __syncthreads();
    if (threadIdx.x == 0) g_is64 = !bad;
}

__global__ void k_convert_hist(const int* __restrict__ ei) {
    int i = blockIdx.x * blockDim.x + threadIdx.x;
    if (i >= Ee) return;
    int s, d;
    if (g_is64) { s = ei[2 * i]; d = ei[2 * (Ee + i)]; }
    else        { s = ei[i];     d = ei[Ee + i]; }
    s = min(max(s, 0), Nn - 1);
    d = min(max(d, 0), Nn - 1);
    g_src[i] = s;
    g_dst[i] = d;
    atomicAdd(&g_cnt[d], 1);
}

// ---------------- CSR build --------------------------------------------------
__global__ void k_scan_block() {
    __shared__ int sh[1024];
    int t = threadIdx.x;
    int idx = blockIdx.x * 1024 + t;
    int v = (idx < Nn) ? g_cnt[idx] : 0;
    sh[t] = v;
    __syncthreads();
    for (int o = 1; o < 1024; o <<= 1) {
        int add = (t >= o) ? sh[t - o] : 0;
        __syncthreads();
        sh[t] += add;
        __syncthreads();
    }
    if (idx < Nn) g_rowptr[idx] = sh[t] - v;
    if (t == 1023) g_bsum[blockIdx.x] = sh[1023];
}

__global__ void k_scan_top() {          // 1 block x 128 threads, NB <= 128
    int t = threadIdx.x;
    int lane = t & 31, w = t >> 5;
    int v = (t < NB) ? g_bsum[t] : 0;
    int x = v;
#pragma unroll
    for (int o = 1; o < 32; o <<= 1) {
        int y = __shfl_up_sync(0xffffffff, x, o);
        if (lane >= o) x += y;
    }
    __shared__ int ws[4];
    if (lane == 31) ws[w] = x;
    __syncthreads();
    int add = 0;
    for (int i = 0; i < w; i++) add += ws[i];
    if (t < NB) g_boff[t] = x + add - v;   // exclusive
}

__global__ void k_scan_add() {
    int i = blockIdx.x * blockDim.x + threadIdx.x;
    if (i >= Nn) return;
    int r = g_rowptr[i] + g_boff[i >> 10];
    g_rowptr[i] = r;
    g_woff[i] = r;
}

__global__ void k_fill() {
    int i = blockIdx.x * blockDim.x + threadIdx.x;
    if (i >= Ee) return;
    int d = g_dst[i];
    int pos = atomicAdd(&g_woff[d], 1);
    g_csrc[pos] = g_src[i];
}

// ---------------- weight preconversion (transposed bf16 hi/lo) ---------------
__global__ void k_prepW1(const float* __restrict__ W1) {
    int i = blockIdx.x * blockDim.x + threadIdx.x;
    if (i < 128 * 128) {
        int k = i >> 7, n = i & 127;
        float v = W1[i];
        __nv_bfloat16 hi = __float2bfloat16(v);
        g_Wt1_hi[n * 128 + k] = hi;
        g_Wt1_lo[n * 128 + k] = __float2bfloat16(v - __bfloat162float(hi));
    }
}

__global__ void k_prepW2(const float* __restrict__ W2) {
    int i = blockIdx.x * blockDim.x + threadIdx.x;
    if (i < 128 * 64) {
        int k = i / 64, n = i % 64;
        float v = W2[i];
        __nv_bfloat16 hi = __float2bfloat16(v);
        g_Wt2_hi[n * 128 + k] = hi;
        g_Wt2_lo[n * 128 + k] = __float2bfloat16(v - __bfloat162float(hi));
    }
}

// ---------------- bf16 split-K TC GEMM: double-buffered, cp.async B ----------
template<int BN, int NH>
__global__ void __launch_bounds__(256, 2)
gemm_tc(const float* __restrict__ A,
        const __nv_bfloat16* __restrict__ Bt_hi,
        const __nv_bfloat16* __restrict__ Bt_lo,
        __half* __restrict__ C, int M,
        const float* __restrict__ a_src, const float* __restrict__ a_dst,
        float* __restrict__ es_out, float* __restrict__ ed_out) {
    constexpr int K  = 128;
    constexpr int BK = 32;
    constexpr int AP = 40;
    constexpr int NBW = BN / 16;
    constexpr int ASZ = 128 * AP;        // elems per A buffer
    constexpr int BSZ = BN * AP;         // elems per B buffer

    extern __shared__ __align__(16) char dsm[];
    __nv_bfloat16* AsHi = (__nv_bfloat16*)dsm;
    __nv_bfloat16* AsLo = AsHi + 2 * ASZ;
    __nv_bfloat16* BsHi = AsLo + 2 * ASZ;
    __nv_bfloat16* BsLo = BsHi + 2 * BSZ;
    float* sm_es = (float*)(BsLo + 2 * BSZ);
    float* sm_ed = sm_es + 128;

    const int tid  = threadIdx.x;
    const int w    = tid >> 5;
    const int lane = tid & 31;
    const int g    = lane >> 2;
    const int q    = lane & 3;
    const int wrow = (w >> 1) * 32;
    const int n0w  = (w & 1) * (BN / 2);
    const int row0 = blockIdx.x * 128;

    const int a_r = lane & 15;
    const int a_k = (lane >> 4) * 8;
    const int b_r = (lane & 7) + ((lane >> 4) * 8);
    const int b_k = ((lane >> 3) & 1) * 8;

    const uint32_t sAhi = (uint32_t)__cvta_generic_to_shared(AsHi);
    const uint32_t sAlo = (uint32_t)__cvta_generic_to_shared(AsLo);
    const uint32_t sBhi = (uint32_t)__cvta_generic_to_shared(BsHi);
    const uint32_t sBlo = (uint32_t)__cvta_generic_to_shared(BsLo);

    float c[2][NBW][4];
#pragma unroll
    for (int m = 0; m < 2; m++)
#pragma unroll
        for (int nb = 0; nb < NBW; nb++)
#pragma unroll
            for (int j = 0; j < 4; j++) c[m][nb][j] = 0.f;

    float4 va[4];

    // ---- helpers (lambdas) ----
    auto loadA = [&](int kt) {
#pragma unroll
        for (int it = 0; it < 4; it++) {
            int i = tid + it * 256;
            int row = i >> 3, kq = i & 7;
            int gr = row0 + row;
            va[it] = make_float4(0.f, 0.f, 0.f, 0.f);
            if (gr < M) va[it] = *(const float4*)(A + (size_t)gr * K + kt + kq * 4);
        }
    };
    auto storeA = [&](int buf) {
#pragma unroll
        for (int it = 0; it < 4; it++) {
            int i = tid + it * 256;
            int row = i >> 3, kq = i & 7;
            int base = buf * ASZ + row * AP + kq * 4;
            float4 v = va[it];
            __nv_bfloat16 h0 = __float2bfloat16(v.x), h1b = __float2bfloat16(v.y);
            __nv_bfloat16 h2 = __float2bfloat16(v.z), h3 = __float2bfloat16(v.w);
            *(__nv_bfloat162*)&AsHi[base]     = __nv_bfloat162(h0, h1b);
            *(__nv_bfloat162*)&AsHi[base + 2] = __nv_bfloat162(h2, h3);
            *(__nv_bfloat162*)&AsLo[base] = __nv_bfloat162(
                __float2bfloat16(v.x - __bfloat162float(h0)),
                __float2bfloat16(v.y - __bfloat162float(h1b)));
            *(__nv_bfloat162*)&AsLo[base + 2] = __nv_bfloat162(
                __float2bfloat16(v.z - __bfloat162float(h2)),
                __float2bfloat16(v.w - __bfloat162float(h3)));
        }
    };
    auto loadB_async = [&](int buf, int kt) {
#pragma unroll
        for (int it = 0; it < BN * 4 / 256; it++) {
            int i = tid + it * 256;
            int n = i >> 2, j = i & 3;
            uint32_t so = (uint32_t)((buf * BSZ + n * AP + j * 8) * 2);
            cp16(sBhi + so, Bt_hi + n * 128 + kt + j * 8);
            cp16(sBlo + so, Bt_lo + n * 128 + kt + j * 8);
        }
        asm volatile("cp.async.commit_group;" ::: "memory");
    };

    // ---- prologue: tile 0 into buffer 0 ----
    loadB_async(0, 0);
    loadA(0);
    storeA(0);
    asm volatile("cp.async.wait_group 0;" ::: "memory");
    __syncthreads();

    // ---- pipelined main loop over 4 k-tiles ----
#pragma unroll
    for (int t = 0; t < K / BK; t++) {
        const int buf = t & 1;
        const int nxt = buf ^ 1;
        if (t < K / BK - 1) {
            loadB_async(nxt, (t + 1) * BK);
            loadA((t + 1) * BK);
        }
        // compute on smem[buf]
#pragma unroll
        for (int kk = 0; kk < BK; kk += 16) {
            uint32_t ahi[2][4], alo[2][4];
#pragma unroll
            for (int m = 0; m < 2; m++) {
                uint32_t off = (uint32_t)((buf * ASZ + (wrow + m * 16 + a_r) * AP + kk + a_k) * 2);
                ldsm4(ahi[m], sAhi + off);
                ldsm4(alo[m], sAlo + off);
            }
#pragma unroll
            for (int nbp = 0; nbp < NBW / 2; nbp++) {
                int nb = 2 * nbp;
                uint32_t off = (uint32_t)((buf * BSZ + (n0w + nb * 8 + b_r) * AP + kk + b_k) * 2);
                uint32_t bh[4], bl[4];
                ldsm4(bh, sBhi + off);
                ldsm4(bl, sBlo + off);
#pragma unroll
                for (int m = 0; m < 2; m++) {
                    mma_bf16(c[m][nb],     ahi[m][0], ahi[m][1], ahi[m][2], ahi[m][3], bh[0], bh[1]);
                    mma_bf16(c[m][nb],     ahi[m][0], ahi[m][1], ahi[m][2], ahi[m][3], bl[0], bl[1]);
                    mma_bf16(c[m][nb],     alo[m][0], alo[m][1], alo[m][2], alo[m][3], bh[0], bh[1]);
                    mma_bf16(c[m][nb + 1], ahi[m][0], ahi[m][1], ahi[m][2], ahi[m][3], bh[2], bh[3]);
                    mma_bf16(c[m][nb + 1], ahi[m][0], ahi[m][1], ahi[m][2], ahi[m][3], bl[2], bl[3]);
                    mma_bf16(c[m][nb + 1], alo[m][0], alo[m][1], alo[m][2], alo[m][3], bh[2], bh[3]);
                }
            }
        }
        if (t < K / BK - 1) {
            storeA(nxt);
            asm volatile("cp.async.wait_group 0;" ::: "memory");
        }
        __syncthreads();
    }

    // ---- C store (fp16) ----
#pragma unroll
    for (int m = 0; m < 2; m++) {
#pragma unroll
        for (int nb = 0; nb < NBW; nb++) {
            int row = row0 + wrow + m * 16 + g;
            int col = n0w + nb * 8 + 2 * q;
            if (row < M)
                *(__half2*)(C + (size_t)row * BN + col) =
                    __floats2half2_rn(c[m][nb][0], c[m][nb][1]);
            if (row + 8 < M)
                *(__half2*)(C + (size_t)(row + 8) * BN + col) =
                    __floats2half2_rn(c[m][nb][2], c[m][nb][3]);
        }
    }

    // ---- fused score epilogue (fp32 fragments) ----
    constexpr int HW = (NH == 4) ? 2 : 1;
    float pes[4][HW], ped[4][HW];
#pragma unroll
    for (int r = 0; r < 4; r++)
#pragma unroll
        for (int hh = 0; hh < HW; hh++) { pes[r][hh] = 0.f; ped[r][hh] = 0.f; }
#pragma unroll
    for (int nb = 0; nb < NBW; nb++) {
        int colg = n0w + nb * 8 + 2 * q;
        float a0s = a_src[colg], a1s = a_src[colg + 1];
        float a0d = a_dst[colg], a1d = a_dst[colg + 1];
        int hh = (NH == 4) ? (nb / (NBW / 2)) : 0;
#pragma unroll
        for (int m = 0; m < 2; m++) {
            pes[m * 2 + 0][hh] += c[m][nb][0] * a0s + c[m][nb][1] * a1s;
            pes[m * 2 + 1][hh] += c[m][nb][2] * a0s + c[m][nb][3] * a1s;
            ped[m * 2 + 0][hh] += c[m][nb][0] * a0d + c[m][nb][1] * a1d;
            ped[m * 2 + 1][hh] += c[m][nb][2] * a0d + c[m][nb][3] * a1d;
        }
    }
#pragma unroll
    for (int r = 0; r < 4; r++)
#pragma unroll
        for (int hh = 0; hh < HW; hh++) {
            pes[r][hh] += __shfl_xor_sync(0xffffffff, pes[r][hh], 1);
            pes[r][hh] += __shfl_xor_sync(0xffffffff, pes[r][hh], 2);
            ped[r][hh] += __shfl_xor_sync(0xffffffff, ped[r][hh], 1);
            ped[r][hh] += __shfl_xor_sync(0xffffffff, ped[r][hh], 2);
        }

    if (NH == 4) {
        if (q == 0) {
#pragma unroll
            for (int r = 0; r < 4; r++) {
                int row = row0 + wrow + (r >> 1) * 16 + g + (r & 1) * 8;
                if (row < M) {
                    int hb = (n0w / 32);
                    es_out[row * 4 + hb]     = pes[r][0];
                    es_out[row * 4 + hb + 1] = pes[r][1];
                    ed_out[row * 4 + hb]     = ped[r][0];
                    ed_out[row * 4 + hb + 1] = ped[r][1];
                }
            }
        }
    } else {
        if ((w & 1) && q == 0) {
#pragma unroll
            for (int r = 0; r < 4; r++) {
                int lr = wrow + (r >> 1) * 16 + g + (r & 1) * 8;
                sm_es[lr] = pes[r][0];
                sm_ed[lr] = ped[r][0];
            }
        }
        __syncthreads();
        if (!(w & 1) && q == 0) {
#pragma unroll
            for (int r = 0; r < 4; r++) {
                int lr = wrow + (r >> 1) * 16 + g + (r & 1) * 8;
                int row = row0 + lr;
                if (row < M) {
                    es_out[row] = pes[r][0] + sm_es[lr];
                    ed_out[row] = ped[r][0] + sm_ed[lr];
                }
            }
        }
    }
}

// ---------------- gather-based message passes (round-10 proven bodies) -------
__global__ void msg1_k(const float* __restrict__ b1) {
    int d = (blockIdx.x * blockDim.x + threadIdx.x) >> 5;
    int l = threadIdx.x & 31;
    if (d >= Nn) return;
    int h = l >> 3;
    const float* es = (const float*)g_es1;
    float edh = ((const float*)&g_ed1[d])[h];
    int start = g_rowptr[d];
    int end = start + g_cnt[d];

    float4 acc;
    float den;
    {
        float w = __expf(lrelu(es[4 * d + h] + edh));
        uint2 u = ((const uint2*)(g_h1h + (size_t)d * F1))[l];
        float2 f01 = __half22float2(*(__half2*)&u.x);
        float2 f23 = __half22float2(*(__half2*)&u.y);
        acc.x = w * f01.x; acc.y = w * f01.y; acc.z = w * f23.x; acc.w = w * f23.y;
        den = w;
    }
    int e = start;
    for (; e + 1 < end; e += 2) {
        int s0 = g_csrc[e], s1 = g_csrc[e + 1];
        float w0 = __expf(lrelu(es[4 * s0 + h] + edh));
        float w1 = __expf(lrelu(es[4 * s1 + h] + edh));
        uint2 u0 = ((const uint2*)(g_h1h + (size_t)s0 * F1))[l];
        uint2 u1 = ((const uint2*)(g_h1h + (size_t)s1 * F1))[l];
        float2 a01 = __half22float2(*(__half2*)&u0.x);
        float2 a23 = __half22float2(*(__half2*)&u0.y);
        float2 b01 = __half22float2(*(__half2*)&u1.x);
        float2 b23 = __half22float2(*(__half2*)&u1.y);
        acc.x += w0 * a01.x + w1 * b01.x;
        acc.y += w0 * a01.y + w1 * b01.y;
        acc.z += w0 * a23.x + w1 * b23.x;
        acc.w += w0 * a23.y + w1 * b23.y;
        den += w0 + w1;
    }
    if (e < end) {
        int s = g_csrc[e];
        float w = __expf(lrelu(es[4 * s + h] + edh));
        uint2 u = ((const uint2*)(g_h1h + (size_t)s * F1))[l];
        float2 f01 = __half22float2(*(__half2*)&u.x);
        float2 f23 = __half22float2(*(__half2*)&u.y);
        acc.x += w * f01.x; acc.y += w * f01.y; acc.z += w * f23.x; acc.w += w * f23.y;
        den += w;
    }
    float inv = 1.f / (den + 1e-16f);
    const float4 bb = ((const float4*)b1)[l];
    float4 o;
    o.x = acc.x * inv + bb.x;
    o.y = acc.y * inv + bb.y;
    o.z = acc.z * inv + bb.z;
    o.w = acc.w * inv + bb.w;
    o.x = o.x > 0.f ? o.x : expm1f(o.x);
    o.y = o.y > 0.f ? o.y : expm1f(o.y);
    o.z = o.z > 0.f ? o.z : expm1f(o.z);
    o.w = o.w > 0.f ? o.w : expm1f(o.w);
    ((float4*)(g_agg1 + (size_t)d * F1))[l] = o;
}

__global__ void msg2_k(float* __restrict__ out, const float* __restrict__ b2) {
    int d = (blockIdx.x * blockDim.x + threadIdx.x) >> 5;
    int l = threadIdx.x & 31;
    if (d >= Nn) return;
    float edh = g_ed2[d];
    int start = g_rowptr[d];
    int end = start + g_cnt[d];

    float2 acc;
    float den;
    {
        float w = __expf(lrelu(g_es2[d] + edh));
        float2 v = __half22float2(((const __half2*)(g_h2h + (size_t)d * OUTF))[l]);
        acc.x = w * v.x; acc.y = w * v.y;
        den = w;
    }
    int e = start;
    for (; e + 1 < end; e += 2) {
        int s0 = g_csrc[e], s1 = g_csrc[e + 1];
        float w0 = __expf(lrelu(g_es2[s0] + edh));
        float w1 = __expf(lrelu(g_es2[s1] + edh));
        float2 v0 = __half22float2(((const __half2*)(g_h2h + (size_t)s0 * OUTF))[l]);
        float2 v1 = __half22float2(((const __half2*)(g_h2h + (size_t)s1 * OUTF))[l]);
        acc.x += w0 * v0.x + w1 * v1.x;
        acc.y += w0 * v0.y + w1 * v1.y;
        den += w0 + w1;
    }
    if (e < end) {
        int s = g_csrc[e];
        float w = __expf(lrelu(g_es2[s] + edh));
        float2 v = __half22float2(((const __half2*)(g_h2h + (size_t)s * OUTF))[l]);
        acc.x += w * v.x; acc.y += w * v.y;
        den += w;
    }
    float inv = 1.f / (den + 1e-16f);
    const float2 bb = ((const float2*)b2)[l];
    float2 o;
    o.x = acc.x * inv + bb.x;
    o.y = acc.y * inv + bb.y;
    ((float2*)(out + (size_t)d * OUTF))[l] = o;
}

// ---------------- launch ----------------------------------------------------
#define DSM1 ((4 * 128 * 40 + 4 * 128 * 40) * 2 / 2 + 1024)   // see below
// BN=128: (2*ASZ + 2*ASZ + 2*BSZ + 2*BSZ) elems * 2B + 1KB = 8*5120*2 + 1024
static const int DSMEM_G1 = 8 * 5120 * 2 + 1024;   // 82944
static const int DSMEM_G2 = (4 * 5120 + 4 * 2560) * 2 + 1024; // 62464

extern "C" void kernel_launch(void* const* d_in, const int* in_sizes, int n_in,
                              void* d_out, int out_size) {
    const float* x   = (const float*)d_in[0];
    const int*   ei  = (const int*)d_in[1];
    const float* W1  = (const float*)d_in[2];
    const float* as1 = (const float*)d_in[3];
    const float* ad1 = (const float*)d_in[4];
    const float* b1  = (const float*)d_in[5];
    const float* W2  = (const float*)d_in[6];
    const float* as2 = (const float*)d_in[7];
    const float* ad2 = (const float*)d_in[8];
    const float* b2  = (const float*)d_in[9];
    float* out = (float*)d_out;

    static cudaStream_t s1;
    static cudaEvent_t ev0, evCSR;
    static bool inited = false;
    static float *p_agg1, *p_es1, *p_ed1, *p_es2, *p_ed2;
    static __half *p_h1h, *p_h2h;
    static __nv_bfloat16 *pW1h, *pW1l, *pW2h, *pW2l;
    static int *p_cnt;
    if (!inited) {
        cudaStreamCreateWithFlags(&s1, cudaStreamNonBlocking);
        cudaEventCreateWithFlags(&ev0,   cudaEventDisableTiming);
        cudaEventCreateWithFlags(&evCSR, cudaEventDisableTiming);
        cudaGetSymbolAddress((void**)&p_h1h,  g_h1h);
        cudaGetSymbolAddress((void**)&p_agg1, g_agg1);
        cudaGetSymbolAddress((void**)&p_h2h,  g_h2h);
        cudaGetSymbolAddress((void**)&p_es1,  g_es1);
        cudaGetSymbolAddress((void**)&p_ed1,  g_ed1);
        cudaGetSymbolAddress((void**)&p_es2,  g_es2);
        cudaGetSymbolAddress((void**)&p_ed2,  g_ed2);
        cudaGetSymbolAddress((void**)&pW1h,   g_Wt1_hi);
        cudaGetSymbolAddress((void**)&pW1l,   g_Wt1_lo);
        cudaGetSymbolAddress((void**)&pW2h,   g_Wt2_hi);
        cudaGetSymbolAddress((void**)&pW2l,   g_Wt2_lo);
        cudaGetSymbolAddress((void**)&p_cnt,  g_cnt);
        cudaFuncSetAttribute(gemm_tc<128, 4>,
                             cudaFuncAttributeMaxDynamicSharedMemorySize, DSMEM_G1);
        cudaFuncSetAttribute(gemm_tc<64, 1>,
                             cudaFuncAttributeMaxDynamicSharedMemorySize, DSMEM_G2);
        inited = true;
    }

    // fork: CSR build chain + W2 prep on s1, concurrent with GEMM1 path
    cudaEventRecord(ev0, 0);
    cudaStreamWaitEvent(s1, ev0, 0);

    k_detect<<<1, 256, 0, s1>>>((const unsigned int*)ei);
    cudaMemsetAsync(p_cnt, 0, Nn * sizeof(int), s1);
    k_prepW2<<<(128 * 64 + 255) / 256, 256, 0, s1>>>(W2);
    k_convert_hist<<<(Ee + 255) / 256, 256, 0, s1>>>(ei);
    k_scan_block<<<NB, 1024, 0, s1>>>();
    k_scan_top<<<1, 128, 0, s1>>>();
    k_scan_add<<<(Nn + 255) / 256, 256, 0, s1>>>();
    k_fill<<<(Ee + 255) / 256, 256, 0, s1>>>();
    cudaEventRecord(evCSR, s1);

    // stream 0: W1 prep + layer-1 GEMM (scores fused)
    k_prepW1<<<(128 * 128 + 255) / 256, 256>>>(W1);
    gemm_tc<128, 4><<<(Nn + 127) / 128, 256, DSMEM_G1>>>(x, pW1h, pW1l, p_h1h, Nn,
                                                         as1, ad1, p_es1, p_ed1);

    // join: msg1 needs CSR
    cudaStreamWaitEvent(0, evCSR, 0);

    // serial (proven) order
    msg1_k<<<(Nn * 32 + 255) / 256, 256>>>(b1);
    gemm_tc<64, 1><<<(Nn + 127) / 128, 256, DSMEM_G2>>>(p_agg1, pW2h, pW2l, p_h2h, Nn,
                                                        as2, ad2, p_es2, p_ed2);
    msg2_k<<<(Nn * 32 + 255) / 256, 256>>>(out, b2);
}